// round 11
// baseline (speedup 1.0000x reference)
#include <cuda_runtime.h>
#include <cuda_bf16.h>
#include <cstdint>
#include <math.h>

#define S_LEN 2048
#define DE    4096
#define HQ    32
#define HKV   8
#define DH    128

// ---------------- scratch (no allocations allowed) ----------------
__device__ float g_q[S_LEN * HQ  * DH];   // [s][h][d], post-rope pre-scaled
__device__ float g_k[S_LEN * HKV * DH];   // [s][kh][d]
__device__ float g_v[S_LEN * HKV * DH];   // [s][kh][d]
__device__ float g_o[S_LEN * HQ  * DH];   // [s][h][d]

// flash bf16 hi/lo planes
__device__ __nv_bfloat16 g_qh[HQ  * S_LEN * DH];
__device__ __nv_bfloat16 g_ql[HQ  * S_LEN * DH];
__device__ __nv_bfloat16 g_kh[HKV * S_LEN * DH];
__device__ __nv_bfloat16 g_kl[HKV * S_LEN * DH];
__device__ __nv_bfloat16 g_vth[HKV * DH * S_LEN];
__device__ __nv_bfloat16 g_vtl[HKV * DH * S_LEN];

#define MMA16816(d, a, b)                                              \
    asm volatile(                                                      \
        "mma.sync.aligned.m16n8k16.row.col.f32.bf16.bf16.f32 "         \
        "{%0,%1,%2,%3}, {%4,%5,%6,%7}, {%8,%9}, {%0,%1,%2,%3};"        \
        : "+f"(d[0]), "+f"(d[1]), "+f"(d[2]), "+f"(d[3])               \
        : "r"(a[0]), "r"(a[1]), "r"(a[2]), "r"(a[3]),                  \
          "r"(b[0]), "r"(b[1]))

#define LDSM4(R, addr)                                                 \
    asm volatile(                                                      \
        "ldmatrix.sync.aligned.m8n8.x4.shared.b16 {%0,%1,%2,%3}, [%4];"\
        : "=r"((R)[0]), "=r"((R)[1]), "=r"((R)[2]), "=r"((R)[3])       \
        : "r"(addr))

__device__ __forceinline__ uint32_t smem_u32(const void* p)
{
    return (uint32_t)__cvta_generic_to_shared(p);
}

__device__ __forceinline__ void split2(float x, __nv_bfloat16* h, __nv_bfloat16* l)
{
    __nv_bfloat16 hh = __float2bfloat16_rn(x);
    *h = hh;
    *l = __float2bfloat16_rn(x - __bfloat162float(hh));
}

__device__ __forceinline__ void split_pack2(float a, float b, uint32_t& ph, uint32_t& pl)
{
    __nv_bfloat162 hp = __floats2bfloat162_rn(a, b);
    ph = *(uint32_t*)&hp;
    float al = a - __bfloat162float(hp.x);
    float bl = b - __bfloat162float(hp.y);
    __nv_bfloat162 lp = __floats2bfloat162_rn(al, bl);
    pl = *(uint32_t*)&lp;
}

// =================================================================
// bf16x3 tensor-core GEMM — R5/R6-proven structure.
// R11 deltas ONLY: BKP 34->40 (16B-aligned rows), fragment loads via
// ldmatrix.x4, A smem fill via packed bf16x2 stores. Same data, same
// layouts, same mma order.
// =================================================================
#define BKP 40
#define PLANE (128 * BKP)
#define STAGE_ELEMS (4 * PLANE)
#define GEMM_SMEM (2 * STAGE_ELEMS * 2)   // 81920 bytes

__global__ __launch_bounds__(256) void gemm_bf16x3(
    const float* __restrict__ A, const float* __restrict__ B,
    float* __restrict__ C, int M, int N, int K)
{
    extern __shared__ __align__(16) char smraw[];
    __nv_bfloat16* sm = (__nv_bfloat16*)smraw;

    const int tid  = threadIdx.x;
    const int wid  = tid >> 5, lane = tid & 31;
    const int wm   = wid >> 2, wn = wid & 3;
    const int lg   = lane >> 2;
    const int lk   = lane & 3;
    const long row0 = (long)blockIdx.y * 128;
    const long col0 = (long)blockIdx.x * 128;

    const float* Aa = A + row0 * K;
    const float* Bb = B + col0;

    // ldmatrix per-lane offsets (bf16 units, added to tile-row base)
    const int a_off = ((lane & 7) + 8 * ((lane >> 3) & 1)) * BKP + (lane >> 4) * 8;
    const int b_off = ((lane & 7) + 8 * (lane >> 4)) * BKP + ((lane >> 3) & 1) * 8;

    float acc[4][4][4];
#pragma unroll
    for (int mt = 0; mt < 4; mt++)
#pragma unroll
        for (int nt = 0; nt < 4; nt++)
#pragma unroll
            for (int e = 0; e < 4; e++) acc[mt][nt][e] = 0.f;

    {
        __nv_bfloat16* Ah = sm;
        __nv_bfloat16* Al = sm + PLANE;
        __nv_bfloat16* Bh = sm + 2 * PLANE;
        __nv_bfloat16* Bl = sm + 3 * PLANE;
#pragma unroll
        for (int t = 0; t < 4; t++) {
            int idx = tid + t * 256;
            int r = idx >> 3, c4 = (idx & 7) << 2;
            float4 v = *(const float4*)(Aa + (long)r * K + c4);
            uint32_t h01, l01, h23, l23;
            split_pack2(v.x, v.y, h01, l01);
            split_pack2(v.z, v.w, h23, l23);
            *(uint32_t*)&Ah[r * BKP + c4]     = h01;
            *(uint32_t*)&Ah[r * BKP + c4 + 2] = h23;
            *(uint32_t*)&Al[r * BKP + c4]     = l01;
            *(uint32_t*)&Al[r * BKP + c4 + 2] = l23;
        }
#pragma unroll
        for (int t = 0; t < 4; t++) {
            int idx = tid + t * 256;
            int r = idx >> 5, c4 = (idx & 31) << 2;
            float4 v = *(const float4*)(Bb + (long)r * N + c4);
            split2(v.x, &Bh[(c4 + 0) * BKP + r], &Bl[(c4 + 0) * BKP + r]);
            split2(v.y, &Bh[(c4 + 1) * BKP + r], &Bl[(c4 + 1) * BKP + r]);
            split2(v.z, &Bh[(c4 + 2) * BKP + r], &Bl[(c4 + 2) * BKP + r]);
            split2(v.w, &Bh[(c4 + 3) * BKP + r], &Bl[(c4 + 3) * BKP + r]);
        }
    }
    __syncthreads();

    const int KT = K / 32;
    int buf = 0;
    for (int kt = 0; kt < KT; kt++) {
        float4 la[4], lb[4];
        const bool has_next = (kt + 1 < KT);
        if (has_next) {
            const int k0 = (kt + 1) * 32;
#pragma unroll
            for (int t = 0; t < 4; t++) {
                int idx = tid + t * 256;
                int r = idx >> 3, c4 = (idx & 7) << 2;
                la[t] = *(const float4*)(Aa + (long)r * K + k0 + c4);
            }
#pragma unroll
            for (int t = 0; t < 4; t++) {
                int idx = tid + t * 256;
                int r = idx >> 5, c4 = (idx & 31) << 2;
                lb[t] = *(const float4*)(Bb + (long)(k0 + r) * N + c4);
            }
        }

        const __nv_bfloat16* Ah = sm + buf * STAGE_ELEMS;
        const __nv_bfloat16* Al = Ah + PLANE;
        const __nv_bfloat16* Bh = Ah + 2 * PLANE;
        const __nv_bfloat16* Bl = Ah + 3 * PLANE;

#pragma unroll
        for (int ks = 0; ks < 32; ks += 16) {
            uint32_t ah[4][4], al[4][4], bh[4][2], bl[4][2];
#pragma unroll
            for (int mt = 0; mt < 4; mt++) {
                LDSM4(ah[mt], smem_u32(&Ah[(wm * 64 + mt * 16) * BKP + ks]) + (a_off << 1));
                LDSM4(al[mt], smem_u32(&Al[(wm * 64 + mt * 16) * BKP + ks]) + (a_off << 1));
            }
#pragma unroll
            for (int p = 0; p < 2; p++) {
                uint32_t th[4], tl[4];
                LDSM4(th, smem_u32(&Bh[(wn * 32 + p * 16) * BKP + ks]) + (b_off << 1));
                LDSM4(tl, smem_u32(&Bl[(wn * 32 + p * 16) * BKP + ks]) + (b_off << 1));
                bh[p * 2][0]     = th[0]; bh[p * 2][1]     = th[1];
                bh[p * 2 + 1][0] = th[2]; bh[p * 2 + 1][1] = th[3];
                bl[p * 2][0]     = tl[0]; bl[p * 2][1]     = tl[1];
                bl[p * 2 + 1][0] = tl[2]; bl[p * 2 + 1][1] = tl[3];
            }
#pragma unroll
            for (int mt = 0; mt < 4; mt++)
#pragma unroll
                for (int nt = 0; nt < 4; nt++) MMA16816(acc[mt][nt], ah[mt], bh[nt]);
#pragma unroll
            for (int mt = 0; mt < 4; mt++)
#pragma unroll
                for (int nt = 0; nt < 4; nt++) MMA16816(acc[mt][nt], ah[mt], bl[nt]);
#pragma unroll
            for (int mt = 0; mt < 4; mt++)
#pragma unroll
                for (int nt = 0; nt < 4; nt++) MMA16816(acc[mt][nt], al[mt], bh[nt]);
        }

        if (has_next) {
            __nv_bfloat16* nAh = sm + (buf ^ 1) * STAGE_ELEMS;
            __nv_bfloat16* nAl = nAh + PLANE;
            __nv_bfloat16* nBh = nAh + 2 * PLANE;
            __nv_bfloat16* nBl = nAh + 3 * PLANE;
#pragma unroll
            for (int t = 0; t < 4; t++) {
                int idx = tid + t * 256;
                int r = idx >> 3, c4 = (idx & 7) << 2;
                uint32_t h01, l01, h23, l23;
                split_pack2(la[t].x, la[t].y, h01, l01);
                split_pack2(la[t].z, la[t].w, h23, l23);
                *(uint32_t*)&nAh[r * BKP + c4]     = h01;
                *(uint32_t*)&nAh[r * BKP + c4 + 2] = h23;
                *(uint32_t*)&nAl[r * BKP + c4]     = l01;
                *(uint32_t*)&nAl[r * BKP + c4 + 2] = l23;
            }
#pragma unroll
            for (int t = 0; t < 4; t++) {
                int idx = tid + t * 256;
                int r = idx >> 5, c4 = (idx & 31) << 2;
                split2(lb[t].x, &nBh[(c4 + 0) * BKP + r], &nBl[(c4 + 0) * BKP + r]);
                split2(lb[t].y, &nBh[(c4 + 1) * BKP + r], &nBl[(c4 + 1) * BKP + r]);
                split2(lb[t].z, &nBh[(c4 + 2) * BKP + r], &nBl[(c4 + 2) * BKP + r]);
                split2(lb[t].w, &nBh[(c4 + 3) * BKP + r], &nBl[(c4 + 3) * BKP + r]);
            }
        }
        __syncthreads();
        buf ^= 1;
    }

#pragma unroll
    for (int mt = 0; mt < 4; mt++) {
        long r = row0 + wm * 64 + mt * 16 + lg;
#pragma unroll
        for (int nt = 0; nt < 4; nt++) {
            long c = col0 + wn * 32 + nt * 8 + lk * 2;
            *(float2*)&C[r * N + c]       = make_float2(acc[mt][nt][0], acc[mt][nt][1]);
            *(float2*)&C[(r + 8) * N + c] = make_float2(acc[mt][nt][2], acc[mt][nt][3]);
        }
    }
}

// =================================================================
// RoPE in-place on fp32 q,k (+ fold 1/sqrt(DH) into q)  [R6 verbatim]
// =================================================================
__global__ void rope_kernel(const float* __restrict__ cs)
{
    const int total = S_LEN * (HQ + HKV) * (DH / 2);
    int idx = blockIdx.x * blockDim.x + threadIdx.x;
    if (idx >= total) return;
    const int d = idx & 63;
    const int h = (idx >> 6) % (HQ + HKV);
    const int s = idx / (64 * (HQ + HKV));

    const float c  = cs[s * 64 + d];
    const float sn = cs[S_LEN * 64 + s * 64 + d];

    float* base;
    float sc;
    if (h < HQ) { base = g_q + ((long)s * HQ + h) * DH;         sc = 0.08838834764831845f; }
    else        { base = g_k + ((long)s * HKV + (h - HQ)) * DH; sc = 1.0f; }

    const float x1 = base[d], x2 = base[d + 64];
    base[d]      = (x1 * c + x2 * sn) * sc;
    base[d + 64] = (-x1 * sn + x2 * c) * sc;
}

// =================================================================
// Convert post-rope fp32 q/k/v into bf16 hi/lo planes  [R6 verbatim]
// =================================================================
__global__ void convert_kernel()
{
    const long QN = (long)S_LEN * HQ * DH;
    const long KN = (long)S_LEN * HKV * DH;
    long i = (long)blockIdx.x * blockDim.x + threadIdx.x;
    if (i < QN) {
        int d = (int)(i % DH);
        long t = i / DH;
        int h = (int)(t % HQ);
        int s = (int)(t / HQ);
        long o = ((long)h * S_LEN + s) * DH + d;
        split2(g_q[i], &g_qh[o], &g_ql[o]);
    } else if (i < QN + KN) {
        long j = i - QN;
        int d = (int)(j % DH);
        long t = j / DH;
        int kh = (int)(t % HKV);
        int s = (int)(t / HKV);
        long o = ((long)kh * S_LEN + s) * DH + d;
        split2(g_k[j], &g_kh[o], &g_kl[o]);
    } else if (i < QN + 2 * KN) {
        long j = i - QN - KN;
        int d = (int)(j % DH);
        long t = j / DH;
        int kh = (int)(t % HKV);
        int s = (int)(t / HKV);
        long o = ((long)kh * DH + d) * S_LEN + s;
        split2(g_v[j], &g_vth[o], &g_vtl[o]);
    }
}

// =================================================================
// Tensor-core causal flash attention  [R10 verbatim, passing]
// =================================================================
#define QSTR 136
#define VSTR 72
#define FL_SMEM ((2 * 128 * QSTR + 2 * 64 * QSTR + 2 * 128 * VSTR) * 2)  // 141312 B

__global__ __launch_bounds__(256) void flash_mma_kernel()
{
    extern __shared__ __align__(16) __nv_bfloat16 sb[];
    __nv_bfloat16* sQh = sb;                    // 128 x 136
    __nv_bfloat16* sQl = sQh + 128 * QSTR;      // 128 x 136
    __nv_bfloat16* sKh = sQl + 128 * QSTR;      //  64 x 136
    __nv_bfloat16* sKl = sKh + 64 * QSTR;       //  64 x 136
    __nv_bfloat16* sVh = sKl + 64 * QSTR;       // 128 x 72  ([d][key])
    __nv_bfloat16* sVl = sVh + 128 * VSTR;      // 128 x 72

    const int tid  = threadIdx.x;
    const int wid  = tid >> 5, lane = tid & 31;
    const int lg   = lane >> 2, lk = lane & 3;
    const int qt   = gridDim.x - 1 - blockIdx.x;
    const int h    = blockIdx.y;
    const int kvh  = h >> 2;
    const int q0   = qt * 128;
    const int wr0  = q0 + wid * 16;

    {
        const __nv_bfloat16* gqh = g_qh + ((long)h * S_LEN + q0) * DH;
        const __nv_bfloat16* gql = g_ql + ((long)h * S_LEN + q0) * DH;
#pragma unroll
        for (int t = 0; t < 8; t++) {
            int idx = tid + t * 256;
            int r = idx >> 4, c8 = (idx & 15) << 3;
            *(uint4*)&sQh[r * QSTR + c8] = *(const uint4*)&gqh[r * DH + c8];
            *(uint4*)&sQl[r * QSTR + c8] = *(const uint4*)&gql[r * DH + c8];
        }
    }

    float m_i[2] = {-INFINITY, -INFINITY};
    float l_i[2] = {0.f, 0.f};
    float o_acc[16][4];
#pragma unroll
    for (int nt = 0; nt < 16; nt++)
#pragma unroll
        for (int e = 0; e < 4; e++) o_acc[nt][e] = 0.f;

    const int KT = 2 * qt + 2;
    for (int kt = 0; kt < KT; kt++) {
        const int k0 = kt * 64;
        __syncthreads();
        {
            const __nv_bfloat16* gkh = g_kh + ((long)kvh * S_LEN + k0) * DH;
            const __nv_bfloat16* gkl = g_kl + ((long)kvh * S_LEN + k0) * DH;
#pragma unroll
            for (int t = 0; t < 4; t++) {
                int idx = tid + t * 256;
                int r = idx >> 4, c8 = (idx & 15) << 3;
                *(uint4*)&sKh[r * QSTR + c8] = *(const uint4*)&gkh[r * DH + c8];
                *(uint4*)&sKl[r * QSTR + c8] = *(const uint4*)&gkl[r * DH + c8];
            }
            const __nv_bfloat16* gvh = g_vth + (long)kvh * DH * S_LEN + k0;
            const __nv_bfloat16* gvl = g_vtl + (long)kvh * DH * S_LEN + k0;
#pragma unroll
            for (int t = 0; t < 4; t++) {
                int idx = tid + t * 256;
                int r = idx >> 3, c8 = (idx & 7) << 3;
                *(uint4*)&sVh[r * VSTR + c8] = *(const uint4*)&gvh[(long)r * S_LEN + c8];
                *(uint4*)&sVl[r * VSTR + c8] = *(const uint4*)&gvl[(long)r * S_LEN + c8];
            }
        }
        __syncthreads();

        if (k0 <= wr0 + 15) {
            float sacc[8][4];
#pragma unroll
            for (int nt = 0; nt < 8; nt++)
#pragma unroll
                for (int e = 0; e < 4; e++) sacc[nt][e] = 0.f;

#pragma unroll
            for (int ks = 0; ks < 8; ks++) {
                uint32_t aqh[4], aql[4];
                const int ab = (wid * 16 + lg) * QSTR + ks * 16 + lk * 2;
                aqh[0] = *(const uint32_t*)&sQh[ab];
                aqh[1] = *(const uint32_t*)&sQh[ab + 8 * QSTR];
                aqh[2] = *(const uint32_t*)&sQh[ab + 8];
                aqh[3] = *(const uint32_t*)&sQh[ab + 8 * QSTR + 8];
                aql[0] = *(const uint32_t*)&sQl[ab];
                aql[1] = *(const uint32_t*)&sQl[ab + 8 * QSTR];
                aql[2] = *(const uint32_t*)&sQl[ab + 8];
                aql[3] = *(const uint32_t*)&sQl[ab + 8 * QSTR + 8];
#pragma unroll
                for (int nt = 0; nt < 8; nt++) {
                    uint32_t bh[2], bl[2];
                    const int bb = (nt * 8 + lg) * QSTR + ks * 16 + lk * 2;
                    bh[0] = *(const uint32_t*)&sKh[bb];
                    bh[1] = *(const uint32_t*)&sKh[bb + 8];
                    bl[0] = *(const uint32_t*)&sKl[bb];
                    bl[1] = *(const uint32_t*)&sKl[bb + 8];
                    MMA16816(sacc[nt], aqh, bh);
                    MMA16816(sacc[nt], aqh, bl);
                    MMA16816(sacc[nt], aql, bh);
                }
            }

            if (k0 + 63 > wr0) {
                const int rg0 = wr0 + lg, rg1 = wr0 + lg + 8;
#pragma unroll
                for (int nt = 0; nt < 8; nt++) {
                    const int j = k0 + nt * 8 + lk * 2;
                    if (j     > rg0) sacc[nt][0] = -INFINITY;
                    if (j + 1 > rg0) sacc[nt][1] = -INFINITY;
                    if (j     > rg1) sacc[nt][2] = -INFINITY;
                    if (j + 1 > rg1) sacc[nt][3] = -INFINITY;
                }
            }

            float mx0 = -INFINITY, mx1 = -INFINITY;
#pragma unroll
            for (int nt = 0; nt < 8; nt++) {
                mx0 = fmaxf(mx0, fmaxf(sacc[nt][0], sacc[nt][1]));
                mx1 = fmaxf(mx1, fmaxf(sacc[nt][2], sacc[nt][3]));
            }
            mx0 = fmaxf(mx0, __shfl_xor_sync(0xffffffffu, mx0, 1));
            mx0 = fmaxf(mx0, __shfl_xor_sync(0xffffffffu, mx0, 2));
            mx1 = fmaxf(mx1, __shfl_xor_sync(0xffffffffu, mx1, 1));
            mx1 = fmaxf(mx1, __shfl_xor_sync(0xffffffffu, mx1, 2));

            const float mn0 = fmaxf(m_i[0], mx0);
            const float mn1 = fmaxf(m_i[1], mx1);
            const float al0 = __expf(m_i[0] - mn0);
            const float al1 = __expf(m_i[1] - mn1);

            float rs0 = 0.f, rs1 = 0.f;
#pragma unroll
            for (int nt = 0; nt < 8; nt++) {
                float p0 = __expf(sacc[nt][0] - mn0);
                float p1 = __expf(sacc[nt][1] - mn0);
                float p2 = __expf(sacc[nt][2] - mn1);
                float p3 = __expf(sacc[nt][3] - mn1);
                sacc[nt][0] = p0; sacc[nt][1] = p1; sacc[nt][2] = p2; sacc[nt][3] = p3;
                rs0 += p0 + p1; rs1 += p2 + p3;
            }
            rs0 += __shfl_xor_sync(0xffffffffu, rs0, 1);
            rs0 += __shfl_xor_sync(0xffffffffu, rs0, 2);
            rs1 += __shfl_xor_sync(0xffffffffu, rs1, 1);
            rs1 += __shfl_xor_sync(0xffffffffu, rs1, 2);

            l_i[0] = l_i[0] * al0 + rs0;  m_i[0] = mn0;
            l_i[1] = l_i[1] * al1 + rs1;  m_i[1] = mn1;

#pragma unroll
            for (int nt = 0; nt < 16; nt++) {
                o_acc[nt][0] *= al0; o_acc[nt][1] *= al0;
                o_acc[nt][2] *= al1; o_acc[nt][3] *= al1;
            }

#pragma unroll
            for (int ks2 = 0; ks2 < 4; ks2++) {
                const int t0 = 2 * ks2, t1 = 2 * ks2 + 1;
                uint32_t ph[4], pl[4];
                split_pack2(sacc[t0][0], sacc[t0][1], ph[0], pl[0]);
                split_pack2(sacc[t0][2], sacc[t0][3], ph[1], pl[1]);
                split_pack2(sacc[t1][0], sacc[t1][1], ph[2], pl[2]);
                split_pack2(sacc[t1][2], sacc[t1][3], ph[3], pl[3]);
#pragma unroll
                for (int nt = 0; nt < 16; nt++) {
                    uint32_t bh[2], bl[2];
                    const int bb = (nt * 8 + lg) * VSTR + ks2 * 16 + lk * 2;
                    bh[0] = *(const uint32_t*)&sVh[bb];
                    bh[1] = *(const uint32_t*)&sVh[bb + 8];
                    bl[0] = *(const uint32_t*)&sVl[bb];
                    bl[1] = *(const uint32_t*)&sVl[bb + 8];
                    MMA16816(o_acc[nt], ph, bh);
                    MMA16816(o_acc[nt], ph, bl);
                    MMA16816(o_acc[nt], pl, bh);
                }
            }
        }
    }

    const float inv0 = 1.0f / l_i[0];
    const float inv1 = 1.0f / l_i[1];
    const int r0 = wr0 + lg;
#pragma unroll
    for (int nt = 0; nt < 16; nt++) {
        const int c = nt * 8 + lk * 2;
        *(float2*)&g_o[((long)r0 * HQ + h) * DH + c] =
            make_float2(o_acc[nt][0] * inv0, o_acc[nt][1] * inv0);
        *(float2*)&g_o[((long)(r0 + 8) * HQ + h) * DH + c] =
            make_float2(o_acc[nt][2] * inv1, o_acc[nt][3] * inv1);
    }
}

// =================================================================
extern "C" void kernel_launch(void* const* d_in, const int* in_sizes, int n_in,
                              void* d_out, int out_size)
{
    const float* x  = (const float*)d_in[0];
    const float* cs = (const float*)d_in[1];
    const float* wq = (const float*)d_in[2];
    const float* wk = (const float*)d_in[3];
    const float* wv = (const float*)d_in[4];
    const float* wo = (const float*)d_in[5];
    float* out = (float*)d_out;

    float *q, *k, *v, *o;
    cudaGetSymbolAddress((void**)&q, g_q);
    cudaGetSymbolAddress((void**)&k, g_k);
    cudaGetSymbolAddress((void**)&v, g_v);
    cudaGetSymbolAddress((void**)&o, g_o);

    cudaFuncSetAttribute((const void*)gemm_bf16x3,
                         cudaFuncAttributeMaxDynamicSharedMemorySize, GEMM_SMEM);
    cudaFuncSetAttribute((const void*)flash_mma_kernel,
                         cudaFuncAttributeMaxDynamicSharedMemorySize, FL_SMEM);

    // QKV projections (tensor-core bf16x3)
    gemm_bf16x3<<<dim3(DE / 128, S_LEN / 128), 256, GEMM_SMEM>>>(x, wq, q, S_LEN, DE, DE);
    gemm_bf16x3<<<dim3((HKV * DH) / 128, S_LEN / 128), 256, GEMM_SMEM>>>(x, wk, k, S_LEN, HKV * DH, DE);
    gemm_bf16x3<<<dim3((HKV * DH) / 128, S_LEN / 128), 256, GEMM_SMEM>>>(x, wv, v, S_LEN, HKV * DH, DE);

    // RoPE (+ fold 1/sqrt(DH) into q)
    const int rope_total = S_LEN * (HQ + HKV) * (DH / 2);
    rope_kernel<<<(rope_total + 255) / 256, 256>>>(cs);

    // split into bf16 hi/lo planes (and transpose V)
    const long conv_total = (long)S_LEN * HQ * DH + 2L * S_LEN * HKV * DH;
    convert_kernel<<<(int)((conv_total + 255) / 256), 256>>>();

    // tensor-core causal flash attention (128-row q tiles)
    flash_mma_kernel<<<dim3(S_LEN / 128, HQ), 256, FL_SMEM>>>();

    // output projection (tensor-core bf16x3)
    gemm_bf16x3<<<dim3(DE / 128, S_LEN / 128), 256, GEMM_SMEM>>>(o, wo, out, S_LEN, DE, DE);
}

// round 13
// speedup vs baseline: 1.5316x; 1.5316x over previous
#include <cuda_runtime.h>
#include <cuda_bf16.h>
#include <cstdint>
#include <math.h>

#define S_LEN 2048
#define DE    4096
#define HQ    32
#define HKV   8
#define DH    128

// ---------------- scratch (no allocations allowed) ----------------
__device__ float g_q[S_LEN * HQ  * DH];   // [s][h][d], raw Q projection
__device__ float g_k[S_LEN * HKV * DH];   // [s][kh][d]
__device__ float g_v[S_LEN * HKV * DH];   // [s][kh][d]
__device__ float g_o[S_LEN * HQ  * DH];   // [s][h][d]

// flash bf16 hi/lo planes
__device__ __nv_bfloat16 g_qh[HQ  * S_LEN * DH];
__device__ __nv_bfloat16 g_ql[HQ  * S_LEN * DH];
__device__ __nv_bfloat16 g_kh[HKV * S_LEN * DH];
__device__ __nv_bfloat16 g_kl[HKV * S_LEN * DH];
__device__ __nv_bfloat16 g_vth[HKV * DH * S_LEN];
__device__ __nv_bfloat16 g_vtl[HKV * DH * S_LEN];

#define MMA16816(d, a, b)                                              \
    asm volatile(                                                      \
        "mma.sync.aligned.m16n8k16.row.col.f32.bf16.bf16.f32 "         \
        "{%0,%1,%2,%3}, {%4,%5,%6,%7}, {%8,%9}, {%0,%1,%2,%3};"        \
        : "+f"(d[0]), "+f"(d[1]), "+f"(d[2]), "+f"(d[3])               \
        : "r"(a[0]), "r"(a[1]), "r"(a[2]), "r"(a[3]),                  \
          "r"(b[0]), "r"(b[1]))

__device__ __forceinline__ void split2(float x, __nv_bfloat16* h, __nv_bfloat16* l)
{
    __nv_bfloat16 hh = __float2bfloat16_rn(x);
    *h = hh;
    *l = __float2bfloat16_rn(x - __bfloat162float(hh));
}

__device__ __forceinline__ void split_pack2(float a, float b, uint32_t& ph, uint32_t& pl)
{
    __nv_bfloat162 hp = __floats2bfloat162_rn(a, b);
    ph = *(uint32_t*)&hp;
    float al = a - __bfloat162float(hp.x);
    float bl = b - __bfloat162float(hp.y);
    __nv_bfloat162 lp = __floats2bfloat162_rn(al, bl);
    pl = *(uint32_t*)&lp;
}

// =================================================================
// bf16x3 tensor-core GEMM (R5/R6/R10 verbatim — PROVEN, DO NOT TOUCH)
// =================================================================
#define BKP 34
#define PLANE (128 * BKP)
#define STAGE_ELEMS (4 * PLANE)
#define GEMM_SMEM (2 * STAGE_ELEMS * 2)

__global__ __launch_bounds__(256) void gemm_bf16x3(
    const float* __restrict__ A, const float* __restrict__ B,
    float* __restrict__ C, int M, int N, int K)
{
    extern __shared__ __align__(16) char smraw[];
    __nv_bfloat16* sm = (__nv_bfloat16*)smraw;

    const int tid  = threadIdx.x;
    const int wid  = tid >> 5, lane = tid & 31;
    const int wm   = wid >> 2, wn = wid & 3;
    const int lg   = lane >> 2;
    const int lk   = lane & 3;
    const long row0 = (long)blockIdx.y * 128;
    const long col0 = (long)blockIdx.x * 128;

    const float* Aa = A + row0 * K;
    const float* Bb = B + col0;

    float acc[4][4][4];
#pragma unroll
    for (int mt = 0; mt < 4; mt++)
#pragma unroll
        for (int nt = 0; nt < 4; nt++)
#pragma unroll
            for (int e = 0; e < 4; e++) acc[mt][nt][e] = 0.f;

    {
        __nv_bfloat16* Ah = sm;
        __nv_bfloat16* Al = sm + PLANE;
        __nv_bfloat16* Bh = sm + 2 * PLANE;
        __nv_bfloat16* Bl = sm + 3 * PLANE;
#pragma unroll
        for (int t = 0; t < 4; t++) {
            int idx = tid + t * 256;
            int r = idx >> 3, c4 = (idx & 7) << 2;
            float4 v = *(const float4*)(Aa + (long)r * K + c4);
            split2(v.x, &Ah[r * BKP + c4 + 0], &Al[r * BKP + c4 + 0]);
            split2(v.y, &Ah[r * BKP + c4 + 1], &Al[r * BKP + c4 + 1]);
            split2(v.z, &Ah[r * BKP + c4 + 2], &Al[r * BKP + c4 + 2]);
            split2(v.w, &Ah[r * BKP + c4 + 3], &Al[r * BKP + c4 + 3]);
        }
#pragma unroll
        for (int t = 0; t < 4; t++) {
            int idx = tid + t * 256;
            int r = idx >> 5, c4 = (idx & 31) << 2;
            float4 v = *(const float4*)(Bb + (long)r * N + c4);
            split2(v.x, &Bh[(c4 + 0) * BKP + r], &Bl[(c4 + 0) * BKP + r]);
            split2(v.y, &Bh[(c4 + 1) * BKP + r], &Bl[(c4 + 1) * BKP + r]);
            split2(v.z, &Bh[(c4 + 2) * BKP + r], &Bl[(c4 + 2) * BKP + r]);
            split2(v.w, &Bh[(c4 + 3) * BKP + r], &Bl[(c4 + 3) * BKP + r]);
        }
    }
    __syncthreads();

    const int KT = K / 32;
    int buf = 0;
    for (int kt = 0; kt < KT; kt++) {
        float4 la[4], lb[4];
        const bool has_next = (kt + 1 < KT);
        if (has_next) {
            const int k0 = (kt + 1) * 32;
#pragma unroll
            for (int t = 0; t < 4; t++) {
                int idx = tid + t * 256;
                int r = idx >> 3, c4 = (idx & 7) << 2;
                la[t] = *(const float4*)(Aa + (long)r * K + k0 + c4);
            }
#pragma unroll
            for (int t = 0; t < 4; t++) {
                int idx = tid + t * 256;
                int r = idx >> 5, c4 = (idx & 31) << 2;
                lb[t] = *(const float4*)(Bb + (long)(k0 + r) * N + c4);
            }
        }

        const __nv_bfloat16* Ah = sm + buf * STAGE_ELEMS;
        const __nv_bfloat16* Al = Ah + PLANE;
        const __nv_bfloat16* Bh = Ah + 2 * PLANE;
        const __nv_bfloat16* Bl = Ah + 3 * PLANE;

#pragma unroll
        for (int ks = 0; ks < 32; ks += 16) {
            uint32_t ah[4][4], al[4][4], bh[4][2], bl[4][2];
#pragma unroll
            for (int mt = 0; mt < 4; mt++) {
                int r = wm * 64 + mt * 16 + lg;
                int base = r * BKP + ks + lk * 2;
                ah[mt][0] = *(const uint32_t*)&Ah[base];
                ah[mt][1] = *(const uint32_t*)&Ah[base + 8 * BKP];
                ah[mt][2] = *(const uint32_t*)&Ah[base + 8];
                ah[mt][3] = *(const uint32_t*)&Ah[base + 8 * BKP + 8];
                al[mt][0] = *(const uint32_t*)&Al[base];
                al[mt][1] = *(const uint32_t*)&Al[base + 8 * BKP];
                al[mt][2] = *(const uint32_t*)&Al[base + 8];
                al[mt][3] = *(const uint32_t*)&Al[base + 8 * BKP + 8];
            }
#pragma unroll
            for (int nt = 0; nt < 4; nt++) {
                int c = wn * 32 + nt * 8 + lg;
                int base = c * BKP + ks + lk * 2;
                bh[nt][0] = *(const uint32_t*)&Bh[base];
                bh[nt][1] = *(const uint32_t*)&Bh[base + 8];
                bl[nt][0] = *(const uint32_t*)&Bl[base];
                bl[nt][1] = *(const uint32_t*)&Bl[base + 8];
            }
#pragma unroll
            for (int mt = 0; mt < 4; mt++)
#pragma unroll
                for (int nt = 0; nt < 4; nt++) MMA16816(acc[mt][nt], ah[mt], bh[nt]);
#pragma unroll
            for (int mt = 0; mt < 4; mt++)
#pragma unroll
                for (int nt = 0; nt < 4; nt++) MMA16816(acc[mt][nt], ah[mt], bl[nt]);
#pragma unroll
            for (int mt = 0; mt < 4; mt++)
#pragma unroll
                for (int nt = 0; nt < 4; nt++) MMA16816(acc[mt][nt], al[mt], bh[nt]);
        }

        if (has_next) {
            __nv_bfloat16* nAh = sm + (buf ^ 1) * STAGE_ELEMS;
            __nv_bfloat16* nAl = nAh + PLANE;
            __nv_bfloat16* nBh = nAh + 2 * PLANE;
            __nv_bfloat16* nBl = nAh + 3 * PLANE;
#pragma unroll
            for (int t = 0; t < 4; t++) {
                int idx = tid + t * 256;
                int r = idx >> 3, c4 = (idx & 7) << 2;
                split2(la[t].x, &nAh[r * BKP + c4 + 0], &nAl[r * BKP + c4 + 0]);
                split2(la[t].y, &nAh[r * BKP + c4 + 1], &nAl[r * BKP + c4 + 1]);
                split2(la[t].z, &nAh[r * BKP + c4 + 2], &nAl[r * BKP + c4 + 2]);
                split2(la[t].w, &nAh[r * BKP + c4 + 3], &nAl[r * BKP + c4 + 3]);
            }
#pragma unroll
            for (int t = 0; t < 4; t++) {
                int idx = tid + t * 256;
                int r = idx >> 5, c4 = (idx & 31) << 2;
                split2(lb[t].x, &nBh[(c4 + 0) * BKP + r], &nBl[(c4 + 0) * BKP + r]);
                split2(lb[t].y, &nBh[(c4 + 1) * BKP + r], &nBl[(c4 + 1) * BKP + r]);
                split2(lb[t].z, &nBh[(c4 + 2) * BKP + r], &nBl[(c4 + 2) * BKP + r]);
                split2(lb[t].w, &nBh[(c4 + 3) * BKP + r], &nBl[(c4 + 3) * BKP + r]);
            }
        }
        __syncthreads();
        buf ^= 1;
    }

#pragma unroll
    for (int mt = 0; mt < 4; mt++) {
        long r = row0 + wm * 64 + mt * 16 + lg;
#pragma unroll
        for (int nt = 0; nt < 4; nt++) {
            long c = col0 + wn * 32 + nt * 8 + lk * 2;
            *(float2*)&C[r * N + c]       = make_float2(acc[mt][nt][0], acc[mt][nt][1]);
            *(float2*)&C[(r + 8) * N + c] = make_float2(acc[mt][nt][2], acc[mt][nt][3]);
        }
    }
}

// =================================================================
// Fused RoPE + split-to-planes. Replaces rope_kernel + convert_kernel.
// q/k: read raw fp32 projection, apply rope (+1/sqrt(DH) on q) in
// registers, split to bf16 hi/lo planes. v: split + transpose.
// Same op composition as before -> numerically identical planes.
// =================================================================
__global__ void rope_convert_kernel(const float* __restrict__ cs)
{
    const long QK_PAIRS = (long)S_LEN * (HQ + HKV) * 64;   // one thread = pair (d, d+64)
    const long VN = (long)S_LEN * HKV * DH;
    long i = (long)blockIdx.x * blockDim.x + threadIdx.x;

    if (i < QK_PAIRS) {
        const int d = (int)(i & 63);
        const int h = (int)((i >> 6) % (HQ + HKV));
        const int s = (int)(i / (64 * (HQ + HKV)));

        const float c  = cs[s * 64 + d];
        const float sn = cs[S_LEN * 64 + s * 64 + d];

        if (h < HQ) {
            const float* base = g_q + ((long)s * HQ + h) * DH;
            const float x1 = base[d], x2 = base[d + 64];
            const float sc = 0.08838834764831845f;  // 1/sqrt(128)
            const float y1 = (x1 * c + x2 * sn) * sc;
            const float y2 = (-x1 * sn + x2 * c) * sc;
            const long o = ((long)h * S_LEN + s) * DH;
            split2(y1, &g_qh[o + d],      &g_ql[o + d]);
            split2(y2, &g_qh[o + d + 64], &g_ql[o + d + 64]);
        } else {
            const int kh = h - HQ;
            const float* base = g_k + ((long)s * HKV + kh) * DH;
            const float x1 = base[d], x2 = base[d + 64];
            const float y1 = x1 * c + x2 * sn;
            const float y2 = -x1 * sn + x2 * c;
            const long o = ((long)kh * S_LEN + s) * DH;
            split2(y1, &g_kh[o + d],      &g_kl[o + d]);
            split2(y2, &g_kh[o + d + 64], &g_kl[o + d + 64]);
        }
    } else if (i < QK_PAIRS + VN) {
        const long j = i - QK_PAIRS;
        const int d = (int)(j % DH);
        const long t = j / DH;
        const int kh = (int)(t % HKV);
        const int s = (int)(t / HKV);
        const long o = ((long)kh * DH + d) * S_LEN + s;   // transposed
        split2(g_v[j], &g_vth[o], &g_vtl[o]);
    }
}

// =================================================================
// Tensor-core causal flash attention  [R10 verbatim, passing]
// =================================================================
#define QSTR 136
#define VSTR 72
#define FL_SMEM ((2 * 128 * QSTR + 2 * 64 * QSTR + 2 * 128 * VSTR) * 2)  // 141312 B

__global__ __launch_bounds__(256) void flash_mma_kernel()
{
    extern __shared__ __align__(16) __nv_bfloat16 sb[];
    __nv_bfloat16* sQh = sb;                    // 128 x 136
    __nv_bfloat16* sQl = sQh + 128 * QSTR;      // 128 x 136
    __nv_bfloat16* sKh = sQl + 128 * QSTR;      //  64 x 136
    __nv_bfloat16* sKl = sKh + 64 * QSTR;       //  64 x 136
    __nv_bfloat16* sVh = sKl + 64 * QSTR;       // 128 x 72  ([d][key])
    __nv_bfloat16* sVl = sVh + 128 * VSTR;      // 128 x 72

    const int tid  = threadIdx.x;
    const int wid  = tid >> 5, lane = tid & 31;
    const int lg   = lane >> 2, lk = lane & 3;
    const int qt   = gridDim.x - 1 - blockIdx.x;
    const int h    = blockIdx.y;
    const int kvh  = h >> 2;
    const int q0   = qt * 128;
    const int wr0  = q0 + wid * 16;

    {
        const __nv_bfloat16* gqh = g_qh + ((long)h * S_LEN + q0) * DH;
        const __nv_bfloat16* gql = g_ql + ((long)h * S_LEN + q0) * DH;
#pragma unroll
        for (int t = 0; t < 8; t++) {
            int idx = tid + t * 256;
            int r = idx >> 4, c8 = (idx & 15) << 3;
            *(uint4*)&sQh[r * QSTR + c8] = *(const uint4*)&gqh[r * DH + c8];
            *(uint4*)&sQl[r * QSTR + c8] = *(const uint4*)&gql[r * DH + c8];
        }
    }

    float m_i[2] = {-INFINITY, -INFINITY};
    float l_i[2] = {0.f, 0.f};
    float o_acc[16][4];
#pragma unroll
    for (int nt = 0; nt < 16; nt++)
#pragma unroll
        for (int e = 0; e < 4; e++) o_acc[nt][e] = 0.f;

    const int KT = 2 * qt + 2;
    for (int kt = 0; kt < KT; kt++) {
        const int k0 = kt * 64;
        __syncthreads();
        {
            const __nv_bfloat16* gkh = g_kh + ((long)kvh * S_LEN + k0) * DH;
            const __nv_bfloat16* gkl = g_kl + ((long)kvh * S_LEN + k0) * DH;
#pragma unroll
            for (int t = 0; t < 4; t++) {
                int idx = tid + t * 256;
                int r = idx >> 4, c8 = (idx & 15) << 3;
                *(uint4*)&sKh[r * QSTR + c8] = *(const uint4*)&gkh[r * DH + c8];
                *(uint4*)&sKl[r * QSTR + c8] = *(const uint4*)&gkl[r * DH + c8];
            }
            const __nv_bfloat16* gvh = g_vth + (long)kvh * DH * S_LEN + k0;
            const __nv_bfloat16* gvl = g_vtl + (long)kvh * DH * S_LEN + k0;
#pragma unroll
            for (int t = 0; t < 4; t++) {
                int idx = tid + t * 256;
                int r = idx >> 3, c8 = (idx & 7) << 3;
                *(uint4*)&sVh[r * VSTR + c8] = *(const uint4*)&gvh[(long)r * S_LEN + c8];
                *(uint4*)&sVl[r * VSTR + c8] = *(const uint4*)&gvl[(long)r * S_LEN + c8];
            }
        }
        __syncthreads();

        if (k0 <= wr0 + 15) {
            float sacc[8][4];
#pragma unroll
            for (int nt = 0; nt < 8; nt++)
#pragma unroll
                for (int e = 0; e < 4; e++) sacc[nt][e] = 0.f;

#pragma unroll
            for (int ks = 0; ks < 8; ks++) {
                uint32_t aqh[4], aql[4];
                const int ab = (wid * 16 + lg) * QSTR + ks * 16 + lk * 2;
                aqh[0] = *(const uint32_t*)&sQh[ab];
                aqh[1] = *(const uint32_t*)&sQh[ab + 8 * QSTR];
                aqh[2] = *(const uint32_t*)&sQh[ab + 8];
                aqh[3] = *(const uint32_t*)&sQh[ab + 8 * QSTR + 8];
                aql[0] = *(const uint32_t*)&sQl[ab];
                aql[1] = *(const uint32_t*)&sQl[ab + 8 * QSTR];
                aql[2] = *(const uint32_t*)&sQl[ab + 8];
                aql[3] = *(const uint32_t*)&sQl[ab + 8 * QSTR + 8];
#pragma unroll
                for (int nt = 0; nt < 8; nt++) {
                    uint32_t bh[2], bl[2];
                    const int bb = (nt * 8 + lg) * QSTR + ks * 16 + lk * 2;
                    bh[0] = *(const uint32_t*)&sKh[bb];
                    bh[1] = *(const uint32_t*)&sKh[bb + 8];
                    bl[0] = *(const uint32_t*)&sKl[bb];
                    bl[1] = *(const uint32_t*)&sKl[bb + 8];
                    MMA16816(sacc[nt], aqh, bh);
                    MMA16816(sacc[nt], aqh, bl);
                    MMA16816(sacc[nt], aql, bh);
                }
            }

            if (k0 + 63 > wr0) {
                const int rg0 = wr0 + lg, rg1 = wr0 + lg + 8;
#pragma unroll
                for (int nt = 0; nt < 8; nt++) {
                    const int j = k0 + nt * 8 + lk * 2;
                    if (j     > rg0) sacc[nt][0] = -INFINITY;
                    if (j + 1 > rg0) sacc[nt][1] = -INFINITY;
                    if (j     > rg1) sacc[nt][2] = -INFINITY;
                    if (j + 1 > rg1) sacc[nt][3] = -INFINITY;
                }
            }

            float mx0 = -INFINITY, mx1 = -INFINITY;
#pragma unroll
            for (int nt = 0; nt < 8; nt++) {
                mx0 = fmaxf(mx0, fmaxf(sacc[nt][0], sacc[nt][1]));
                mx1 = fmaxf(mx1, fmaxf(sacc[nt][2], sacc[nt][3]));
            }
            mx0 = fmaxf(mx0, __shfl_xor_sync(0xffffffffu, mx0, 1));
            mx0 = fmaxf(mx0, __shfl_xor_sync(0xffffffffu, mx0, 2));
            mx1 = fmaxf(mx1, __shfl_xor_sync(0xffffffffu, mx1, 1));
            mx1 = fmaxf(mx1, __shfl_xor_sync(0xffffffffu, mx1, 2));

            const float mn0 = fmaxf(m_i[0], mx0);
            const float mn1 = fmaxf(m_i[1], mx1);
            const float al0 = __expf(m_i[0] - mn0);
            const float al1 = __expf(m_i[1] - mn1);

            float rs0 = 0.f, rs1 = 0.f;
#pragma unroll
            for (int nt = 0; nt < 8; nt++) {
                float p0 = __expf(sacc[nt][0] - mn0);
                float p1 = __expf(sacc[nt][1] - mn0);
                float p2 = __expf(sacc[nt][2] - mn1);
                float p3 = __expf(sacc[nt][3] - mn1);
                sacc[nt][0] = p0; sacc[nt][1] = p1; sacc[nt][2] = p2; sacc[nt][3] = p3;
                rs0 += p0 + p1; rs1 += p2 + p3;
            }
            rs0 += __shfl_xor_sync(0xffffffffu, rs0, 1);
            rs0 += __shfl_xor_sync(0xffffffffu, rs0, 2);
            rs1 += __shfl_xor_sync(0xffffffffu, rs1, 1);
            rs1 += __shfl_xor_sync(0xffffffffu, rs1, 2);

            l_i[0] = l_i[0] * al0 + rs0;  m_i[0] = mn0;
            l_i[1] = l_i[1] * al1 + rs1;  m_i[1] = mn1;

#pragma unroll
            for (int nt = 0; nt < 16; nt++) {
                o_acc[nt][0] *= al0; o_acc[nt][1] *= al0;
                o_acc[nt][2] *= al1; o_acc[nt][3] *= al1;
            }

#pragma unroll
            for (int ks2 = 0; ks2 < 4; ks2++) {
                const int t0 = 2 * ks2, t1 = 2 * ks2 + 1;
                uint32_t ph[4], pl[4];
                split_pack2(sacc[t0][0], sacc[t0][1], ph[0], pl[0]);
                split_pack2(sacc[t0][2], sacc[t0][3], ph[1], pl[1]);
                split_pack2(sacc[t1][0], sacc[t1][1], ph[2], pl[2]);
                split_pack2(sacc[t1][2], sacc[t1][3], ph[3], pl[3]);
#pragma unroll
                for (int nt = 0; nt < 16; nt++) {
                    uint32_t bh[2], bl[2];
                    const int bb = (nt * 8 + lg) * VSTR + ks2 * 16 + lk * 2;
                    bh[0] = *(const uint32_t*)&sVh[bb];
                    bh[1] = *(const uint32_t*)&sVh[bb + 8];
                    bl[0] = *(const uint32_t*)&sVl[bb];
                    bl[1] = *(const uint32_t*)&sVl[bb + 8];
                    MMA16816(o_acc[nt], ph, bh);
                    MMA16816(o_acc[nt], ph, bl);
                    MMA16816(o_acc[nt], pl, bh);
                }
            }
        }
    }

    const float inv0 = 1.0f / l_i[0];
    const float inv1 = 1.0f / l_i[1];
    const int r0 = wr0 + lg;
#pragma unroll
    for (int nt = 0; nt < 16; nt++) {
        const int c = nt * 8 + lk * 2;
        *(float2*)&g_o[((long)r0 * HQ + h) * DH + c] =
            make_float2(o_acc[nt][0] * inv0, o_acc[nt][1] * inv0);
        *(float2*)&g_o[((long)(r0 + 8) * HQ + h) * DH + c] =
            make_float2(o_acc[nt][2] * inv1, o_acc[nt][3] * inv1);
    }
}

// =================================================================
extern "C" void kernel_launch(void* const* d_in, const int* in_sizes, int n_in,
                              void* d_out, int out_size)
{
    const float* x  = (const float*)d_in[0];
    const float* cs = (const float*)d_in[1];
    const float* wq = (const float*)d_in[2];
    const float* wk = (const float*)d_in[3];
    const float* wv = (const float*)d_in[4];
    const float* wo = (const float*)d_in[5];
    float* out = (float*)d_out;

    float *q, *k, *v, *o;
    cudaGetSymbolAddress((void**)&q, g_q);
    cudaGetSymbolAddress((void**)&k, g_k);
    cudaGetSymbolAddress((void**)&v, g_v);
    cudaGetSymbolAddress((void**)&o, g_o);

    cudaFuncSetAttribute((const void*)gemm_bf16x3,
                         cudaFuncAttributeMaxDynamicSharedMemorySize, GEMM_SMEM);
    cudaFuncSetAttribute((const void*)flash_mma_kernel,
                         cudaFuncAttributeMaxDynamicSharedMemorySize, FL_SMEM);

    // QKV projections (tensor-core bf16x3) — R10 launch pattern, DO NOT TOUCH
    gemm_bf16x3<<<dim3(DE / 128, S_LEN / 128), 256, GEMM_SMEM>>>(x, wq, q, S_LEN, DE, DE);
    gemm_bf16x3<<<dim3((HKV * DH) / 128, S_LEN / 128), 256, GEMM_SMEM>>>(x, wk, k, S_LEN, HKV * DH, DE);
    gemm_bf16x3<<<dim3((HKV * DH) / 128, S_LEN / 128), 256, GEMM_SMEM>>>(x, wv, v, S_LEN, HKV * DH, DE);

    // Fused RoPE + plane conversion (one pass over q/k, plus v transpose)
    const long rc_total = (long)S_LEN * (HQ + HKV) * 64 + (long)S_LEN * HKV * DH;
    rope_convert_kernel<<<(int)((rc_total + 255) / 256), 256>>>(cs);

    // tensor-core causal flash attention (128-row q tiles)
    flash_mma_kernel<<<dim3(S_LEN / 128, HQ), 256, FL_SMEM>>>();

    // output projection
    gemm_bf16x3<<<dim3(DE / 128, S_LEN / 128), 256, GEMM_SMEM>>>(o, wo, out, S_LEN, DE, DE);
}

// round 15
// speedup vs baseline: 1.5538x; 1.0145x over previous
#include <cuda_runtime.h>
#include <cuda_bf16.h>
#include <cstdint>
#include <math.h>

#define S_LEN 2048
#define DE    4096
#define HQ    32
#define HKV   8
#define DH    128

// ---------------- scratch (no allocations allowed) ----------------
__device__ float g_q[S_LEN * HQ  * DH];   // [s][h][d], raw Q projection
__device__ float g_k[S_LEN * HKV * DH];   // [s][kh][d]
__device__ float g_v[S_LEN * HKV * DH];   // [s][kh][d]
__device__ float g_o[S_LEN * HQ  * DH];   // [s][h][d]

// flash bf16 hi/lo planes
__device__ __nv_bfloat16 g_qh[HQ  * S_LEN * DH];
__device__ __nv_bfloat16 g_ql[HQ  * S_LEN * DH];
__device__ __nv_bfloat16 g_kh[HKV * S_LEN * DH];
__device__ __nv_bfloat16 g_kl[HKV * S_LEN * DH];
__device__ __nv_bfloat16 g_vth[HKV * DH * S_LEN];
__device__ __nv_bfloat16 g_vtl[HKV * DH * S_LEN];

#define MMA16816(d, a, b)                                              \
    asm volatile(                                                      \
        "mma.sync.aligned.m16n8k16.row.col.f32.bf16.bf16.f32 "         \
        "{%0,%1,%2,%3}, {%4,%5,%6,%7}, {%8,%9}, {%0,%1,%2,%3};"        \
        : "+f"(d[0]), "+f"(d[1]), "+f"(d[2]), "+f"(d[3])               \
        : "r"(a[0]), "r"(a[1]), "r"(a[2]), "r"(a[3]),                  \
          "r"(b[0]), "r"(b[1]))

__device__ __forceinline__ void split2(float x, __nv_bfloat16* h, __nv_bfloat16* l)
{
    __nv_bfloat16 hh = __float2bfloat16_rn(x);
    *h = hh;
    *l = __float2bfloat16_rn(x - __bfloat162float(hh));
}

__device__ __forceinline__ void split_pack2(float a, float b, uint32_t& ph, uint32_t& pl)
{
    __nv_bfloat162 hp = __floats2bfloat162_rn(a, b);
    ph = *(uint32_t*)&hp;
    float al = a - __bfloat162float(hp.x);
    float bl = b - __bfloat162float(hp.y);
    __nv_bfloat162 lp = __floats2bfloat162_rn(al, bl);
    pl = *(uint32_t*)&lp;
}

// =================================================================
// bf16x3 tensor-core GEMM (R10/R13 structure; R15 delta: A-side smem
// fill uses packed bf16x2 stores — proven bit-identical in R11).
// =================================================================
#define BKP 34
#define PLANE (128 * BKP)
#define STAGE_ELEMS (4 * PLANE)
#define GEMM_SMEM (2 * STAGE_ELEMS * 2)

__global__ __launch_bounds__(256) void gemm_bf16x3(
    const float* __restrict__ A, const float* __restrict__ B,
    float* __restrict__ C, int M, int N, int K)
{
    extern __shared__ __align__(16) char smraw[];
    __nv_bfloat16* sm = (__nv_bfloat16*)smraw;

    const int tid  = threadIdx.x;
    const int wid  = tid >> 5, lane = tid & 31;
    const int wm   = wid >> 2, wn = wid & 3;
    const int lg   = lane >> 2;
    const int lk   = lane & 3;
    const long row0 = (long)blockIdx.y * 128;
    const long col0 = (long)blockIdx.x * 128;

    const float* Aa = A + row0 * K;
    const float* Bb = B + col0;

    float acc[4][4][4];
#pragma unroll
    for (int mt = 0; mt < 4; mt++)
#pragma unroll
        for (int nt = 0; nt < 4; nt++)
#pragma unroll
            for (int e = 0; e < 4; e++) acc[mt][nt][e] = 0.f;

    {
        __nv_bfloat16* Ah = sm;
        __nv_bfloat16* Al = sm + PLANE;
        __nv_bfloat16* Bh = sm + 2 * PLANE;
        __nv_bfloat16* Bl = sm + 3 * PLANE;
#pragma unroll
        for (int t = 0; t < 4; t++) {
            int idx = tid + t * 256;
            int r = idx >> 3, c4 = (idx & 7) << 2;
            float4 v = *(const float4*)(Aa + (long)r * K + c4);
            uint32_t h01, l01, h23, l23;
            split_pack2(v.x, v.y, h01, l01);
            split_pack2(v.z, v.w, h23, l23);
            *(uint32_t*)&Ah[r * BKP + c4]     = h01;
            *(uint32_t*)&Ah[r * BKP + c4 + 2] = h23;
            *(uint32_t*)&Al[r * BKP + c4]     = l01;
            *(uint32_t*)&Al[r * BKP + c4 + 2] = l23;
        }
#pragma unroll
        for (int t = 0; t < 4; t++) {
            int idx = tid + t * 256;
            int r = idx >> 5, c4 = (idx & 31) << 2;
            float4 v = *(const float4*)(Bb + (long)r * N + c4);
            split2(v.x, &Bh[(c4 + 0) * BKP + r], &Bl[(c4 + 0) * BKP + r]);
            split2(v.y, &Bh[(c4 + 1) * BKP + r], &Bl[(c4 + 1) * BKP + r]);
            split2(v.z, &Bh[(c4 + 2) * BKP + r], &Bl[(c4 + 2) * BKP + r]);
            split2(v.w, &Bh[(c4 + 3) * BKP + r], &Bl[(c4 + 3) * BKP + r]);
        }
    }
    __syncthreads();

    const int KT = K / 32;
    int buf = 0;
    for (int kt = 0; kt < KT; kt++) {
        float4 la[4], lb[4];
        const bool has_next = (kt + 1 < KT);
        if (has_next) {
            const int k0 = (kt + 1) * 32;
#pragma unroll
            for (int t = 0; t < 4; t++) {
                int idx = tid + t * 256;
                int r = idx >> 3, c4 = (idx & 7) << 2;
                la[t] = *(const float4*)(Aa + (long)r * K + k0 + c4);
            }
#pragma unroll
            for (int t = 0; t < 4; t++) {
                int idx = tid + t * 256;
                int r = idx >> 5, c4 = (idx & 31) << 2;
                lb[t] = *(const float4*)(Bb + (long)(k0 + r) * N + c4);
            }
        }

        const __nv_bfloat16* Ah = sm + buf * STAGE_ELEMS;
        const __nv_bfloat16* Al = Ah + PLANE;
        const __nv_bfloat16* Bh = Ah + 2 * PLANE;
        const __nv_bfloat16* Bl = Ah + 3 * PLANE;

#pragma unroll
        for (int ks = 0; ks < 32; ks += 16) {
            uint32_t ah[4][4], al[4][4], bh[4][2], bl[4][2];
#pragma unroll
            for (int mt = 0; mt < 4; mt++) {
                int r = wm * 64 + mt * 16 + lg;
                int base = r * BKP + ks + lk * 2;
                ah[mt][0] = *(const uint32_t*)&Ah[base];
                ah[mt][1] = *(const uint32_t*)&Ah[base + 8 * BKP];
                ah[mt][2] = *(const uint32_t*)&Ah[base + 8];
                ah[mt][3] = *(const uint32_t*)&Ah[base + 8 * BKP + 8];
                al[mt][0] = *(const uint32_t*)&Al[base];
                al[mt][1] = *(const uint32_t*)&Al[base + 8 * BKP];
                al[mt][2] = *(const uint32_t*)&Al[base + 8];
                al[mt][3] = *(const uint32_t*)&Al[base + 8 * BKP + 8];
            }
#pragma unroll
            for (int nt = 0; nt < 4; nt++) {
                int c = wn * 32 + nt * 8 + lg;
                int base = c * BKP + ks + lk * 2;
                bh[nt][0] = *(const uint32_t*)&Bh[base];
                bh[nt][1] = *(const uint32_t*)&Bh[base + 8];
                bl[nt][0] = *(const uint32_t*)&Bl[base];
                bl[nt][1] = *(const uint32_t*)&Bl[base + 8];
            }
#pragma unroll
            for (int mt = 0; mt < 4; mt++)
#pragma unroll
                for (int nt = 0; nt < 4; nt++) MMA16816(acc[mt][nt], ah[mt], bh[nt]);
#pragma unroll
            for (int mt = 0; mt < 4; mt++)
#pragma unroll
                for (int nt = 0; nt < 4; nt++) MMA16816(acc[mt][nt], ah[mt], bl[nt]);
#pragma unroll
            for (int mt = 0; mt < 4; mt++)
#pragma unroll
                for (int nt = 0; nt < 4; nt++) MMA16816(acc[mt][nt], al[mt], bh[nt]);
        }

        if (has_next) {
            __nv_bfloat16* nAh = sm + (buf ^ 1) * STAGE_ELEMS;
            __nv_bfloat16* nAl = nAh + PLANE;
            __nv_bfloat16* nBh = nAh + 2 * PLANE;
            __nv_bfloat16* nBl = nAh + 3 * PLANE;
#pragma unroll
            for (int t = 0; t < 4; t++) {
                int idx = tid + t * 256;
                int r = idx >> 3, c4 = (idx & 7) << 2;
                uint32_t h01, l01, h23, l23;
                split_pack2(la[t].x, la[t].y, h01, l01);
                split_pack2(la[t].z, la[t].w, h23, l23);
                *(uint32_t*)&nAh[r * BKP + c4]     = h01;
                *(uint32_t*)&nAh[r * BKP + c4 + 2] = h23;
                *(uint32_t*)&nAl[r * BKP + c4]     = l01;
                *(uint32_t*)&nAl[r * BKP + c4 + 2] = l23;
            }
#pragma unroll
            for (int t = 0; t < 4; t++) {
                int idx = tid + t * 256;
                int r = idx >> 5, c4 = (idx & 31) << 2;
                split2(lb[t].x, &nBh[(c4 + 0) * BKP + r], &nBl[(c4 + 0) * BKP + r]);
                split2(lb[t].y, &nBh[(c4 + 1) * BKP + r], &nBl[(c4 + 1) * BKP + r]);
                split2(lb[t].z, &nBh[(c4 + 2) * BKP + r], &nBl[(c4 + 2) * BKP + r]);
                split2(lb[t].w, &nBh[(c4 + 3) * BKP + r], &nBl[(c4 + 3) * BKP + r]);
            }
        }
        __syncthreads();
        buf ^= 1;
    }

#pragma unroll
    for (int mt = 0; mt < 4; mt++) {
        long r = row0 + wm * 64 + mt * 16 + lg;
#pragma unroll
        for (int nt = 0; nt < 4; nt++) {
            long c = col0 + wn * 32 + nt * 8 + lk * 2;
            *(float2*)&C[r * N + c]       = make_float2(acc[mt][nt][0], acc[mt][nt][1]);
            *(float2*)&C[(r + 8) * N + c] = make_float2(acc[mt][nt][2], acc[mt][nt][3]);
        }
    }
}

// =================================================================
// Fused RoPE + split-to-planes  [R13 verbatim — V hi AND lo planes]
// =================================================================
__global__ void rope_convert_kernel(const float* __restrict__ cs)
{
    const long QK_PAIRS = (long)S_LEN * (HQ + HKV) * 64;   // one thread = pair (d, d+64)
    const long VN = (long)S_LEN * HKV * DH;
    long i = (long)blockIdx.x * blockDim.x + threadIdx.x;

    if (i < QK_PAIRS) {
        const int d = (int)(i & 63);
        const int h = (int)((i >> 6) % (HQ + HKV));
        const int s = (int)(i / (64 * (HQ + HKV)));

        const float c  = cs[s * 64 + d];
        const float sn = cs[S_LEN * 64 + s * 64 + d];

        if (h < HQ) {
            const float* base = g_q + ((long)s * HQ + h) * DH;
            const float x1 = base[d], x2 = base[d + 64];
            const float sc = 0.08838834764831845f;  // 1/sqrt(128)
            const float y1 = (x1 * c + x2 * sn) * sc;
            const float y2 = (-x1 * sn + x2 * c) * sc;
            const long o = ((long)h * S_LEN + s) * DH;
            split2(y1, &g_qh[o + d],      &g_ql[o + d]);
            split2(y2, &g_qh[o + d + 64], &g_ql[o + d + 64]);
        } else {
            const int kh = h - HQ;
            const float* base = g_k + ((long)s * HKV + kh) * DH;
            const float x1 = base[d], x2 = base[d + 64];
            const float y1 = x1 * c + x2 * sn;
            const float y2 = -x1 * sn + x2 * c;
            const long o = ((long)kh * S_LEN + s) * DH;
            split2(y1, &g_kh[o + d],      &g_kl[o + d]);
            split2(y2, &g_kh[o + d + 64], &g_kl[o + d + 64]);
        }
    } else if (i < QK_PAIRS + VN) {
        const long j = i - QK_PAIRS;
        const int d = (int)(j % DH);
        const long t = j / DH;
        const int kh = (int)(t % HKV);
        const int s = (int)(t / HKV);
        const long o = ((long)kh * DH + d) * S_LEN + s;   // transposed
        split2(g_v[j], &g_vth[o], &g_vtl[o]);
    }
}

// =================================================================
// Tensor-core causal flash attention  [R13 verbatim, passing]
// =================================================================
#define QSTR 136
#define VSTR 72
#define FL_SMEM ((2 * 128 * QSTR + 2 * 64 * QSTR + 2 * 128 * VSTR) * 2)  // 141312 B

__global__ __launch_bounds__(256) void flash_mma_kernel()
{
    extern __shared__ __align__(16) __nv_bfloat16 sb[];
    __nv_bfloat16* sQh = sb;                    // 128 x 136
    __nv_bfloat16* sQl = sQh + 128 * QSTR;      // 128 x 136
    __nv_bfloat16* sKh = sQl + 128 * QSTR;      //  64 x 136
    __nv_bfloat16* sKl = sKh + 64 * QSTR;       //  64 x 136
    __nv_bfloat16* sVh = sKl + 64 * QSTR;       // 128 x 72  ([d][key])
    __nv_bfloat16* sVl = sVh + 128 * VSTR;      // 128 x 72

    const int tid  = threadIdx.x;
    const int wid  = tid >> 5, lane = tid & 31;
    const int lg   = lane >> 2, lk = lane & 3;
    const int qt   = gridDim.x - 1 - blockIdx.x;
    const int h    = blockIdx.y;
    const int kvh  = h >> 2;
    const int q0   = qt * 128;
    const int wr0  = q0 + wid * 16;

    {
        const __nv_bfloat16* gqh = g_qh + ((long)h * S_LEN + q0) * DH;
        const __nv_bfloat16* gql = g_ql + ((long)h * S_LEN + q0) * DH;
#pragma unroll
        for (int t = 0; t < 8; t++) {
            int idx = tid + t * 256;
            int r = idx >> 4, c8 = (idx & 15) << 3;
            *(uint4*)&sQh[r * QSTR + c8] = *(const uint4*)&gqh[r * DH + c8];
            *(uint4*)&sQl[r * QSTR + c8] = *(const uint4*)&gql[r * DH + c8];
        }
    }

    float m_i[2] = {-INFINITY, -INFINITY};
    float l_i[2] = {0.f, 0.f};
    float o_acc[16][4];
#pragma unroll
    for (int nt = 0; nt < 16; nt++)
#pragma unroll
        for (int e = 0; e < 4; e++) o_acc[nt][e] = 0.f;

    const int KT = 2 * qt + 2;
    for (int kt = 0; kt < KT; kt++) {
        const int k0 = kt * 64;
        __syncthreads();
        {
            const __nv_bfloat16* gkh = g_kh + ((long)kvh * S_LEN + k0) * DH;
            const __nv_bfloat16* gkl = g_kl + ((long)kvh * S_LEN + k0) * DH;
#pragma unroll
            for (int t = 0; t < 4; t++) {
                int idx = tid + t * 256;
                int r = idx >> 4, c8 = (idx & 15) << 3;
                *(uint4*)&sKh[r * QSTR + c8] = *(const uint4*)&gkh[r * DH + c8];
                *(uint4*)&sKl[r * QSTR + c8] = *(const uint4*)&gkl[r * DH + c8];
            }
            const __nv_bfloat16* gvh = g_vth + (long)kvh * DH * S_LEN + k0;
            const __nv_bfloat16* gvl = g_vtl + (long)kvh * DH * S_LEN + k0;
#pragma unroll
            for (int t = 0; t < 4; t++) {
                int idx = tid + t * 256;
                int r = idx >> 3, c8 = (idx & 7) << 3;
                *(uint4*)&sVh[r * VSTR + c8] = *(const uint4*)&gvh[(long)r * S_LEN + c8];
                *(uint4*)&sVl[r * VSTR + c8] = *(const uint4*)&gvl[(long)r * S_LEN + c8];
            }
        }
        __syncthreads();

        if (k0 <= wr0 + 15) {
            float sacc[8][4];
#pragma unroll
            for (int nt = 0; nt < 8; nt++)
#pragma unroll
                for (int e = 0; e < 4; e++) sacc[nt][e] = 0.f;

#pragma unroll
            for (int ks = 0; ks < 8; ks++) {
                uint32_t aqh[4], aql[4];
                const int ab = (wid * 16 + lg) * QSTR + ks * 16 + lk * 2;
                aqh[0] = *(const uint32_t*)&sQh[ab];
                aqh[1] = *(const uint32_t*)&sQh[ab + 8 * QSTR];
                aqh[2] = *(const uint32_t*)&sQh[ab + 8];
                aqh[3] = *(const uint32_t*)&sQh[ab + 8 * QSTR + 8];
                aql[0] = *(const uint32_t*)&sQl[ab];
                aql[1] = *(const uint32_t*)&sQl[ab + 8 * QSTR];
                aql[2] = *(const uint32_t*)&sQl[ab + 8];
                aql[3] = *(const uint32_t*)&sQl[ab + 8 * QSTR + 8];
#pragma unroll
                for (int nt = 0; nt < 8; nt++) {
                    uint32_t bh[2], bl[2];
                    const int bb = (nt * 8 + lg) * QSTR + ks * 16 + lk * 2;
                    bh[0] = *(const uint32_t*)&sKh[bb];
                    bh[1] = *(const uint32_t*)&sKh[bb + 8];
                    bl[0] = *(const uint32_t*)&sKl[bb];
                    bl[1] = *(const uint32_t*)&sKl[bb + 8];
                    MMA16816(sacc[nt], aqh, bh);
                    MMA16816(sacc[nt], aqh, bl);
                    MMA16816(sacc[nt], aql, bh);
                }
            }

            if (k0 + 63 > wr0) {
                const int rg0 = wr0 + lg, rg1 = wr0 + lg + 8;
#pragma unroll
                for (int nt = 0; nt < 8; nt++) {
                    const int j = k0 + nt * 8 + lk * 2;
                    if (j     > rg0) sacc[nt][0] = -INFINITY;
                    if (j + 1 > rg0) sacc[nt][1] = -INFINITY;
                    if (j     > rg1) sacc[nt][2] = -INFINITY;
                    if (j + 1 > rg1) sacc[nt][3] = -INFINITY;
                }
            }

            float mx0 = -INFINITY, mx1 = -INFINITY;
#pragma unroll
            for (int nt = 0; nt < 8; nt++) {
                mx0 = fmaxf(mx0, fmaxf(sacc[nt][0], sacc[nt][1]));
                mx1 = fmaxf(mx1, fmaxf(sacc[nt][2], sacc[nt][3]));
            }
            mx0 = fmaxf(mx0, __shfl_xor_sync(0xffffffffu, mx0, 1));
            mx0 = fmaxf(mx0, __shfl_xor_sync(0xffffffffu, mx0, 2));
            mx1 = fmaxf(mx1, __shfl_xor_sync(0xffffffffu, mx1, 1));
            mx1 = fmaxf(mx1, __shfl_xor_sync(0xffffffffu, mx1, 2));

            const float mn0 = fmaxf(m_i[0], mx0);
            const float mn1 = fmaxf(m_i[1], mx1);
            const float al0 = __expf(m_i[0] - mn0);
            const float al1 = __expf(m_i[1] - mn1);

            float rs0 = 0.f, rs1 = 0.f;
#pragma unroll
            for (int nt = 0; nt < 8; nt++) {
                float p0 = __expf(sacc[nt][0] - mn0);
                float p1 = __expf(sacc[nt][1] - mn0);
                float p2 = __expf(sacc[nt][2] - mn1);
                float p3 = __expf(sacc[nt][3] - mn1);
                sacc[nt][0] = p0; sacc[nt][1] = p1; sacc[nt][2] = p2; sacc[nt][3] = p3;
                rs0 += p0 + p1; rs1 += p2 + p3;
            }
            rs0 += __shfl_xor_sync(0xffffffffu, rs0, 1);
            rs0 += __shfl_xor_sync(0xffffffffu, rs0, 2);
            rs1 += __shfl_xor_sync(0xffffffffu, rs1, 1);
            rs1 += __shfl_xor_sync(0xffffffffu, rs1, 2);

            l_i[0] = l_i[0] * al0 + rs0;  m_i[0] = mn0;
            l_i[1] = l_i[1] * al1 + rs1;  m_i[1] = mn1;

#pragma unroll
            for (int nt = 0; nt < 16; nt++) {
                o_acc[nt][0] *= al0; o_acc[nt][1] *= al0;
                o_acc[nt][2] *= al1; o_acc[nt][3] *= al1;
            }

#pragma unroll
            for (int ks2 = 0; ks2 < 4; ks2++) {
                const int t0 = 2 * ks2, t1 = 2 * ks2 + 1;
                uint32_t ph[4], pl[4];
                split_pack2(sacc[t0][0], sacc[t0][1], ph[0], pl[0]);
                split_pack2(sacc[t0][2], sacc[t0][3], ph[1], pl[1]);
                split_pack2(sacc[t1][0], sacc[t1][1], ph[2], pl[2]);
                split_pack2(sacc[t1][2], sacc[t1][3], ph[3], pl[3]);
#pragma unroll
                for (int nt = 0; nt < 16; nt++) {
                    uint32_t bh[2], bl[2];
                    const int bb = (nt * 8 + lg) * VSTR + ks2 * 16 + lk * 2;
                    bh[0] = *(const uint32_t*)&sVh[bb];
                    bh[1] = *(const uint32_t*)&sVh[bb + 8];
                    bl[0] = *(const uint32_t*)&sVl[bb];
                    bl[1] = *(const uint32_t*)&sVl[bb + 8];
                    MMA16816(o_acc[nt], ph, bh);
                    MMA16816(o_acc[nt], ph, bl);
                    MMA16816(o_acc[nt], pl, bh);
                }
            }
        }
    }

    const float inv0 = 1.0f / l_i[0];
    const float inv1 = 1.0f / l_i[1];
    const int r0 = wr0 + lg;
#pragma unroll
    for (int nt = 0; nt < 16; nt++) {
        const int c = nt * 8 + lk * 2;
        *(float2*)&g_o[((long)r0 * HQ + h) * DH + c] =
            make_float2(o_acc[nt][0] * inv0, o_acc[nt][1] * inv0);
        *(float2*)&g_o[((long)(r0 + 8) * HQ + h) * DH + c] =
            make_float2(o_acc[nt][2] * inv1, o_acc[nt][3] * inv1);
    }
}

// =================================================================
extern "C" void kernel_launch(void* const* d_in, const int* in_sizes, int n_in,
                              void* d_out, int out_size)
{
    const float* x  = (const float*)d_in[0];
    const float* cs = (const float*)d_in[1];
    const float* wq = (const float*)d_in[2];
    const float* wk = (const float*)d_in[3];
    const float* wv = (const float*)d_in[4];
    const float* wo = (const float*)d_in[5];
    float* out = (float*)d_out;

    float *q, *k, *v, *o;
    cudaGetSymbolAddress((void**)&q, g_q);
    cudaGetSymbolAddress((void**)&k, g_k);
    cudaGetSymbolAddress((void**)&v, g_v);
    cudaGetSymbolAddress((void**)&o, g_o);

    cudaFuncSetAttribute((const void*)gemm_bf16x3,
                         cudaFuncAttributeMaxDynamicSharedMemorySize, GEMM_SMEM);
    cudaFuncSetAttribute((const void*)flash_mma_kernel,
                         cudaFuncAttributeMaxDynamicSharedMemorySize, FL_SMEM);

    // QKV projections (tensor-core bf16x3) — R10 launch pattern, DO NOT TOUCH
    gemm_bf16x3<<<dim3(DE / 128, S_LEN / 128), 256, GEMM_SMEM>>>(x, wq, q, S_LEN, DE, DE);
    gemm_bf16x3<<<dim3((HKV * DH) / 128, S_LEN / 128), 256, GEMM_SMEM>>>(x, wk, k, S_LEN, HKV * DH, DE);
    gemm_bf16x3<<<dim3((HKV * DH) / 128, S_LEN / 128), 256, GEMM_SMEM>>>(x, wv, v, S_LEN, HKV * DH, DE);

    // Fused RoPE + plane conversion (V: hi and lo planes)
    const long rc_total = (long)S_LEN * (HQ + HKV) * 64 + (long)S_LEN * HKV * DH;
    rope_convert_kernel<<<(int)((rc_total + 255) / 256), 256>>>(cs);

    // tensor-core causal flash attention (128-row q tiles, PV bf16x3)
    flash_mma_kernel<<<dim3(S_LEN / 128, HQ), 256, FL_SMEM>>>();

    // output projection
    gemm_bf16x3<<<dim3(DE / 128, S_LEN / 128), 256, GEMM_SMEM>>>(o, wo, out, S_LEN, DE, DE);
}

// round 16
// speedup vs baseline: 1.5564x; 1.0017x over previous
#include <cuda_runtime.h>
#include <cuda_bf16.h>
#include <cstdint>
#include <math.h>

#define S_LEN 2048
#define DE    4096
#define HQ    32
#define HKV   8
#define DH    128

// ---------------- scratch (no allocations allowed) ----------------
__device__ float g_q[S_LEN * HQ  * DH];   // [s][h][d], raw Q projection
__device__ float g_k[S_LEN * HKV * DH];   // [s][kh][d]
__device__ float g_v[S_LEN * HKV * DH];   // [s][kh][d]
__device__ float g_o[S_LEN * HQ  * DH];   // [s][h][d]

// flash bf16 hi/lo planes
__device__ __nv_bfloat16 g_qh[HQ  * S_LEN * DH];
__device__ __nv_bfloat16 g_ql[HQ  * S_LEN * DH];
__device__ __nv_bfloat16 g_kh[HKV * S_LEN * DH];
__device__ __nv_bfloat16 g_kl[HKV * S_LEN * DH];
__device__ __nv_bfloat16 g_vth[HKV * DH * S_LEN];
__device__ __nv_bfloat16 g_vtl[HKV * DH * S_LEN];

#define MMA16816(d, a, b)                                              \
    asm volatile(                                                      \
        "mma.sync.aligned.m16n8k16.row.col.f32.bf16.bf16.f32 "         \
        "{%0,%1,%2,%3}, {%4,%5,%6,%7}, {%8,%9}, {%0,%1,%2,%3};"        \
        : "+f"(d[0]), "+f"(d[1]), "+f"(d[2]), "+f"(d[3])               \
        : "r"(a[0]), "r"(a[1]), "r"(a[2]), "r"(a[3]),                  \
          "r"(b[0]), "r"(b[1]))

__device__ __forceinline__ void split2(float x, __nv_bfloat16* h, __nv_bfloat16* l)
{
    __nv_bfloat16 hh = __float2bfloat16_rn(x);
    *h = hh;
    *l = __float2bfloat16_rn(x - __bfloat162float(hh));
}

__device__ __forceinline__ void split_pack2(float a, float b, uint32_t& ph, uint32_t& pl)
{
    __nv_bfloat162 hp = __floats2bfloat162_rn(a, b);
    ph = *(uint32_t*)&hp;
    float al = a - __bfloat162float(hp.x);
    float bl = b - __bfloat162float(hp.y);
    __nv_bfloat162 lp = __floats2bfloat162_rn(al, bl);
    pl = *(uint32_t*)&lp;
}

// =================================================================
// bf16x3 tensor-core GEMM  [R15 verbatim — packed A fill, PROVEN]
// =================================================================
#define BKP 34
#define PLANE (128 * BKP)
#define STAGE_ELEMS (4 * PLANE)
#define GEMM_SMEM (2 * STAGE_ELEMS * 2)

__global__ __launch_bounds__(256) void gemm_bf16x3(
    const float* __restrict__ A, const float* __restrict__ B,
    float* __restrict__ C, int M, int N, int K)
{
    extern __shared__ __align__(16) char smraw[];
    __nv_bfloat16* sm = (__nv_bfloat16*)smraw;

    const int tid  = threadIdx.x;
    const int wid  = tid >> 5, lane = tid & 31;
    const int wm   = wid >> 2, wn = wid & 3;
    const int lg   = lane >> 2;
    const int lk   = lane & 3;
    const long row0 = (long)blockIdx.y * 128;
    const long col0 = (long)blockIdx.x * 128;

    const float* Aa = A + row0 * K;
    const float* Bb = B + col0;

    float acc[4][4][4];
#pragma unroll
    for (int mt = 0; mt < 4; mt++)
#pragma unroll
        for (int nt = 0; nt < 4; nt++)
#pragma unroll
            for (int e = 0; e < 4; e++) acc[mt][nt][e] = 0.f;

    {
        __nv_bfloat16* Ah = sm;
        __nv_bfloat16* Al = sm + PLANE;
        __nv_bfloat16* Bh = sm + 2 * PLANE;
        __nv_bfloat16* Bl = sm + 3 * PLANE;
#pragma unroll
        for (int t = 0; t < 4; t++) {
            int idx = tid + t * 256;
            int r = idx >> 3, c4 = (idx & 7) << 2;
            float4 v = *(const float4*)(Aa + (long)r * K + c4);
            uint32_t h01, l01, h23, l23;
            split_pack2(v.x, v.y, h01, l01);
            split_pack2(v.z, v.w, h23, l23);
            *(uint32_t*)&Ah[r * BKP + c4]     = h01;
            *(uint32_t*)&Ah[r * BKP + c4 + 2] = h23;
            *(uint32_t*)&Al[r * BKP + c4]     = l01;
            *(uint32_t*)&Al[r * BKP + c4 + 2] = l23;
        }
#pragma unroll
        for (int t = 0; t < 4; t++) {
            int idx = tid + t * 256;
            int r = idx >> 5, c4 = (idx & 31) << 2;
            float4 v = *(const float4*)(Bb + (long)r * N + c4);
            split2(v.x, &Bh[(c4 + 0) * BKP + r], &Bl[(c4 + 0) * BKP + r]);
            split2(v.y, &Bh[(c4 + 1) * BKP + r], &Bl[(c4 + 1) * BKP + r]);
            split2(v.z, &Bh[(c4 + 2) * BKP + r], &Bl[(c4 + 2) * BKP + r]);
            split2(v.w, &Bh[(c4 + 3) * BKP + r], &Bl[(c4 + 3) * BKP + r]);
        }
    }
    __syncthreads();

    const int KT = K / 32;
    int buf = 0;
    for (int kt = 0; kt < KT; kt++) {
        float4 la[4], lb[4];
        const bool has_next = (kt + 1 < KT);
        if (has_next) {
            const int k0 = (kt + 1) * 32;
#pragma unroll
            for (int t = 0; t < 4; t++) {
                int idx = tid + t * 256;
                int r = idx >> 3, c4 = (idx & 7) << 2;
                la[t] = *(const float4*)(Aa + (long)r * K + k0 + c4);
            }
#pragma unroll
            for (int t = 0; t < 4; t++) {
                int idx = tid + t * 256;
                int r = idx >> 5, c4 = (idx & 31) << 2;
                lb[t] = *(const float4*)(Bb + (long)(k0 + r) * N + c4);
            }
        }

        const __nv_bfloat16* Ah = sm + buf * STAGE_ELEMS;
        const __nv_bfloat16* Al = Ah + PLANE;
        const __nv_bfloat16* Bh = Ah + 2 * PLANE;
        const __nv_bfloat16* Bl = Ah + 3 * PLANE;

#pragma unroll
        for (int ks = 0; ks < 32; ks += 16) {
            uint32_t ah[4][4], al[4][4], bh[4][2], bl[4][2];
#pragma unroll
            for (int mt = 0; mt < 4; mt++) {
                int r = wm * 64 + mt * 16 + lg;
                int base = r * BKP + ks + lk * 2;
                ah[mt][0] = *(const uint32_t*)&Ah[base];
                ah[mt][1] = *(const uint32_t*)&Ah[base + 8 * BKP];
                ah[mt][2] = *(const uint32_t*)&Ah[base + 8];
                ah[mt][3] = *(const uint32_t*)&Ah[base + 8 * BKP + 8];
                al[mt][0] = *(const uint32_t*)&Al[base];
                al[mt][1] = *(const uint32_t*)&Al[base + 8 * BKP];
                al[mt][2] = *(const uint32_t*)&Al[base + 8];
                al[mt][3] = *(const uint32_t*)&Al[base + 8 * BKP + 8];
            }
#pragma unroll
            for (int nt = 0; nt < 4; nt++) {
                int c = wn * 32 + nt * 8 + lg;
                int base = c * BKP + ks + lk * 2;
                bh[nt][0] = *(const uint32_t*)&Bh[base];
                bh[nt][1] = *(const uint32_t*)&Bh[base + 8];
                bl[nt][0] = *(const uint32_t*)&Bl[base];
                bl[nt][1] = *(const uint32_t*)&Bl[base + 8];
            }
#pragma unroll
            for (int mt = 0; mt < 4; mt++)
#pragma unroll
                for (int nt = 0; nt < 4; nt++) MMA16816(acc[mt][nt], ah[mt], bh[nt]);
#pragma unroll
            for (int mt = 0; mt < 4; mt++)
#pragma unroll
                for (int nt = 0; nt < 4; nt++) MMA16816(acc[mt][nt], ah[mt], bl[nt]);
#pragma unroll
            for (int mt = 0; mt < 4; mt++)
#pragma unroll
                for (int nt = 0; nt < 4; nt++) MMA16816(acc[mt][nt], al[mt], bh[nt]);
        }

        if (has_next) {
            __nv_bfloat16* nAh = sm + (buf ^ 1) * STAGE_ELEMS;
            __nv_bfloat16* nAl = nAh + PLANE;
            __nv_bfloat16* nBh = nAh + 2 * PLANE;
            __nv_bfloat16* nBl = nAh + 3 * PLANE;
#pragma unroll
            for (int t = 0; t < 4; t++) {
                int idx = tid + t * 256;
                int r = idx >> 3, c4 = (idx & 7) << 2;
                uint32_t h01, l01, h23, l23;
                split_pack2(la[t].x, la[t].y, h01, l01);
                split_pack2(la[t].z, la[t].w, h23, l23);
                *(uint32_t*)&nAh[r * BKP + c4]     = h01;
                *(uint32_t*)&nAh[r * BKP + c4 + 2] = h23;
                *(uint32_t*)&nAl[r * BKP + c4]     = l01;
                *(uint32_t*)&nAl[r * BKP + c4 + 2] = l23;
            }
#pragma unroll
            for (int t = 0; t < 4; t++) {
                int idx = tid + t * 256;
                int r = idx >> 5, c4 = (idx & 31) << 2;
                split2(lb[t].x, &nBh[(c4 + 0) * BKP + r], &nBl[(c4 + 0) * BKP + r]);
                split2(lb[t].y, &nBh[(c4 + 1) * BKP + r], &nBl[(c4 + 1) * BKP + r]);
                split2(lb[t].z, &nBh[(c4 + 2) * BKP + r], &nBl[(c4 + 2) * BKP + r]);
                split2(lb[t].w, &nBh[(c4 + 3) * BKP + r], &nBl[(c4 + 3) * BKP + r]);
            }
        }
        __syncthreads();
        buf ^= 1;
    }

#pragma unroll
    for (int mt = 0; mt < 4; mt++) {
        long r = row0 + wm * 64 + mt * 16 + lg;
#pragma unroll
        for (int nt = 0; nt < 4; nt++) {
            long c = col0 + wn * 32 + nt * 8 + lk * 2;
            *(float2*)&C[r * N + c]       = make_float2(acc[mt][nt][0], acc[mt][nt][1]);
            *(float2*)&C[(r + 8) * N + c] = make_float2(acc[mt][nt][2], acc[mt][nt][3]);
        }
    }
}

// =================================================================
// Fused RoPE + split-to-planes  [R13 verbatim]
// =================================================================
__global__ void rope_convert_kernel(const float* __restrict__ cs)
{
    const long QK_PAIRS = (long)S_LEN * (HQ + HKV) * 64;
    const long VN = (long)S_LEN * HKV * DH;
    long i = (long)blockIdx.x * blockDim.x + threadIdx.x;

    if (i < QK_PAIRS) {
        const int d = (int)(i & 63);
        const int h = (int)((i >> 6) % (HQ + HKV));
        const int s = (int)(i / (64 * (HQ + HKV)));

        const float c  = cs[s * 64 + d];
        const float sn = cs[S_LEN * 64 + s * 64 + d];

        if (h < HQ) {
            const float* base = g_q + ((long)s * HQ + h) * DH;
            const float x1 = base[d], x2 = base[d + 64];
            const float sc = 0.08838834764831845f;  // 1/sqrt(128)
            const float y1 = (x1 * c + x2 * sn) * sc;
            const float y2 = (-x1 * sn + x2 * c) * sc;
            const long o = ((long)h * S_LEN + s) * DH;
            split2(y1, &g_qh[o + d],      &g_ql[o + d]);
            split2(y2, &g_qh[o + d + 64], &g_ql[o + d + 64]);
        } else {
            const int kh = h - HQ;
            const float* base = g_k + ((long)s * HKV + kh) * DH;
            const float x1 = base[d], x2 = base[d + 64];
            const float y1 = x1 * c + x2 * sn;
            const float y2 = -x1 * sn + x2 * c;
            const long o = ((long)kh * S_LEN + s) * DH;
            split2(y1, &g_kh[o + d],      &g_kl[o + d]);
            split2(y2, &g_kh[o + d + 64], &g_kl[o + d + 64]);
        }
    } else if (i < QK_PAIRS + VN) {
        const long j = i - QK_PAIRS;
        const int d = (int)(j % DH);
        const long t = j / DH;
        const int kh = (int)(t % HKV);
        const int s = (int)(t / HKV);
        const long o = ((long)kh * DH + d) * S_LEN + s;   // transposed
        split2(g_v[j], &g_vth[o], &g_vtl[o]);
    }
}

// =================================================================
// Tensor-core causal flash attention — R13 structure; R16 delta:
// Q fragments hoisted into registers before the kt loop (they are
// loop-invariant per warp). Bit-identical data flow.
// =================================================================
#define QSTR 136
#define VSTR 72
#define FL_SMEM ((2 * 128 * QSTR + 2 * 64 * QSTR + 2 * 128 * VSTR) * 2)  // 141312 B

__global__ __launch_bounds__(256) void flash_mma_kernel()
{
    extern __shared__ __align__(16) __nv_bfloat16 sb[];
    __nv_bfloat16* sQh = sb;                    // 128 x 136
    __nv_bfloat16* sQl = sQh + 128 * QSTR;      // 128 x 136
    __nv_bfloat16* sKh = sQl + 128 * QSTR;      //  64 x 136
    __nv_bfloat16* sKl = sKh + 64 * QSTR;       //  64 x 136
    __nv_bfloat16* sVh = sKl + 64 * QSTR;       // 128 x 72  ([d][key])
    __nv_bfloat16* sVl = sVh + 128 * VSTR;      // 128 x 72

    const int tid  = threadIdx.x;
    const int wid  = tid >> 5, lane = tid & 31;
    const int lg   = lane >> 2, lk = lane & 3;
    const int qt   = gridDim.x - 1 - blockIdx.x;
    const int h    = blockIdx.y;
    const int kvh  = h >> 2;
    const int q0   = qt * 128;
    const int wr0  = q0 + wid * 16;

    {
        const __nv_bfloat16* gqh = g_qh + ((long)h * S_LEN + q0) * DH;
        const __nv_bfloat16* gql = g_ql + ((long)h * S_LEN + q0) * DH;
#pragma unroll
        for (int t = 0; t < 8; t++) {
            int idx = tid + t * 256;
            int r = idx >> 4, c8 = (idx & 15) << 3;
            *(uint4*)&sQh[r * QSTR + c8] = *(const uint4*)&gqh[r * DH + c8];
            *(uint4*)&sQl[r * QSTR + c8] = *(const uint4*)&gql[r * DH + c8];
        }
    }
    __syncthreads();   // Q fill visible before fragment preload

    // ---- preload Q fragments (loop-invariant per warp) ----
    uint32_t aqh_r[8][4], aql_r[8][4];
#pragma unroll
    for (int ks = 0; ks < 8; ks++) {
        const int ab = (wid * 16 + lg) * QSTR + ks * 16 + lk * 2;
        aqh_r[ks][0] = *(const uint32_t*)&sQh[ab];
        aqh_r[ks][1] = *(const uint32_t*)&sQh[ab + 8 * QSTR];
        aqh_r[ks][2] = *(const uint32_t*)&sQh[ab + 8];
        aqh_r[ks][3] = *(const uint32_t*)&sQh[ab + 8 * QSTR + 8];
        aql_r[ks][0] = *(const uint32_t*)&sQl[ab];
        aql_r[ks][1] = *(const uint32_t*)&sQl[ab + 8 * QSTR];
        aql_r[ks][2] = *(const uint32_t*)&sQl[ab + 8];
        aql_r[ks][3] = *(const uint32_t*)&sQl[ab + 8 * QSTR + 8];
    }

    float m_i[2] = {-INFINITY, -INFINITY};
    float l_i[2] = {0.f, 0.f};
    float o_acc[16][4];
#pragma unroll
    for (int nt = 0; nt < 16; nt++)
#pragma unroll
        for (int e = 0; e < 4; e++) o_acc[nt][e] = 0.f;

    const int KT = 2 * qt + 2;
    for (int kt = 0; kt < KT; kt++) {
        const int k0 = kt * 64;
        __syncthreads();
        {
            const __nv_bfloat16* gkh = g_kh + ((long)kvh * S_LEN + k0) * DH;
            const __nv_bfloat16* gkl = g_kl + ((long)kvh * S_LEN + k0) * DH;
#pragma unroll
            for (int t = 0; t < 4; t++) {
                int idx = tid + t * 256;
                int r = idx >> 4, c8 = (idx & 15) << 3;
                *(uint4*)&sKh[r * QSTR + c8] = *(const uint4*)&gkh[r * DH + c8];
                *(uint4*)&sKl[r * QSTR + c8] = *(const uint4*)&gkl[r * DH + c8];
            }
            const __nv_bfloat16* gvh = g_vth + (long)kvh * DH * S_LEN + k0;
            const __nv_bfloat16* gvl = g_vtl + (long)kvh * DH * S_LEN + k0;
#pragma unroll
            for (int t = 0; t < 4; t++) {
                int idx = tid + t * 256;
                int r = idx >> 3, c8 = (idx & 7) << 3;
                *(uint4*)&sVh[r * VSTR + c8] = *(const uint4*)&gvh[(long)r * S_LEN + c8];
                *(uint4*)&sVl[r * VSTR + c8] = *(const uint4*)&gvl[(long)r * S_LEN + c8];
            }
        }
        __syncthreads();

        if (k0 <= wr0 + 15) {
            float sacc[8][4];
#pragma unroll
            for (int nt = 0; nt < 8; nt++)
#pragma unroll
                for (int e = 0; e < 4; e++) sacc[nt][e] = 0.f;

#pragma unroll
            for (int ks = 0; ks < 8; ks++) {
#pragma unroll
                for (int nt = 0; nt < 8; nt++) {
                    uint32_t bh[2], bl[2];
                    const int bb = (nt * 8 + lg) * QSTR + ks * 16 + lk * 2;
                    bh[0] = *(const uint32_t*)&sKh[bb];
                    bh[1] = *(const uint32_t*)&sKh[bb + 8];
                    bl[0] = *(const uint32_t*)&sKl[bb];
                    bl[1] = *(const uint32_t*)&sKl[bb + 8];
                    MMA16816(sacc[nt], aqh_r[ks], bh);
                    MMA16816(sacc[nt], aqh_r[ks], bl);
                    MMA16816(sacc[nt], aql_r[ks], bh);
                }
            }

            if (k0 + 63 > wr0) {
                const int rg0 = wr0 + lg, rg1 = wr0 + lg + 8;
#pragma unroll
                for (int nt = 0; nt < 8; nt++) {
                    const int j = k0 + nt * 8 + lk * 2;
                    if (j     > rg0) sacc[nt][0] = -INFINITY;
                    if (j + 1 > rg0) sacc[nt][1] = -INFINITY;
                    if (j     > rg1) sacc[nt][2] = -INFINITY;
                    if (j + 1 > rg1) sacc[nt][3] = -INFINITY;
                }
            }

            float mx0 = -INFINITY, mx1 = -INFINITY;
#pragma unroll
            for (int nt = 0; nt < 8; nt++) {
                mx0 = fmaxf(mx0, fmaxf(sacc[nt][0], sacc[nt][1]));
                mx1 = fmaxf(mx1, fmaxf(sacc[nt][2], sacc[nt][3]));
            }
            mx0 = fmaxf(mx0, __shfl_xor_sync(0xffffffffu, mx0, 1));
            mx0 = fmaxf(mx0, __shfl_xor_sync(0xffffffffu, mx0, 2));
            mx1 = fmaxf(mx1, __shfl_xor_sync(0xffffffffu, mx1, 1));
            mx1 = fmaxf(mx1, __shfl_xor_sync(0xffffffffu, mx1, 2));

            const float mn0 = fmaxf(m_i[0], mx0);
            const float mn1 = fmaxf(m_i[1], mx1);
            const float al0 = __expf(m_i[0] - mn0);
            const float al1 = __expf(m_i[1] - mn1);

            float rs0 = 0.f, rs1 = 0.f;
#pragma unroll
            for (int nt = 0; nt < 8; nt++) {
                float p0 = __expf(sacc[nt][0] - mn0);
                float p1 = __expf(sacc[nt][1] - mn0);
                float p2 = __expf(sacc[nt][2] - mn1);
                float p3 = __expf(sacc[nt][3] - mn1);
                sacc[nt][0] = p0; sacc[nt][1] = p1; sacc[nt][2] = p2; sacc[nt][3] = p3;
                rs0 += p0 + p1; rs1 += p2 + p3;
            }
            rs0 += __shfl_xor_sync(0xffffffffu, rs0, 1);
            rs0 += __shfl_xor_sync(0xffffffffu, rs0, 2);
            rs1 += __shfl_xor_sync(0xffffffffu, rs1, 1);
            rs1 += __shfl_xor_sync(0xffffffffu, rs1, 2);

            l_i[0] = l_i[0] * al0 + rs0;  m_i[0] = mn0;
            l_i[1] = l_i[1] * al1 + rs1;  m_i[1] = mn1;

#pragma unroll
            for (int nt = 0; nt < 16; nt++) {
                o_acc[nt][0] *= al0; o_acc[nt][1] *= al0;
                o_acc[nt][2] *= al1; o_acc[nt][3] *= al1;
            }

#pragma unroll
            for (int ks2 = 0; ks2 < 4; ks2++) {
                const int t0 = 2 * ks2, t1 = 2 * ks2 + 1;
                uint32_t ph[4], pl[4];
                split_pack2(sacc[t0][0], sacc[t0][1], ph[0], pl[0]);
                split_pack2(sacc[t0][2], sacc[t0][3], ph[1], pl[1]);
                split_pack2(sacc[t1][0], sacc[t1][1], ph[2], pl[2]);
                split_pack2(sacc[t1][2], sacc[t1][3], ph[3], pl[3]);
#pragma unroll
                for (int nt = 0; nt < 16; nt++) {
                    uint32_t bh[2], bl[2];
                    const int bb = (nt * 8 + lg) * VSTR + ks2 * 16 + lk * 2;
                    bh[0] = *(const uint32_t*)&sVh[bb];
                    bh[1] = *(const uint32_t*)&sVh[bb + 8];
                    bl[0] = *(const uint32_t*)&sVl[bb];
                    bl[1] = *(const uint32_t*)&sVl[bb + 8];
                    MMA16816(o_acc[nt], ph, bh);
                    MMA16816(o_acc[nt], ph, bl);
                    MMA16816(o_acc[nt], pl, bh);
                }
            }
        }
    }

    const float inv0 = 1.0f / l_i[0];
    const float inv1 = 1.0f / l_i[1];
    const int r0 = wr0 + lg;
#pragma unroll
    for (int nt = 0; nt < 16; nt++) {
        const int c = nt * 8 + lk * 2;
        *(float2*)&g_o[((long)r0 * HQ + h) * DH + c] =
            make_float2(o_acc[nt][0] * inv0, o_acc[nt][1] * inv0);
        *(float2*)&g_o[((long)(r0 + 8) * HQ + h) * DH + c] =
            make_float2(o_acc[nt][2] * inv1, o_acc[nt][3] * inv1);
    }
}

// =================================================================
extern "C" void kernel_launch(void* const* d_in, const int* in_sizes, int n_in,
                              void* d_out, int out_size)
{
    const float* x  = (const float*)d_in[0];
    const float* cs = (const float*)d_in[1];
    const float* wq = (const float*)d_in[2];
    const float* wk = (const float*)d_in[3];
    const float* wv = (const float*)d_in[4];
    const float* wo = (const float*)d_in[5];
    float* out = (float*)d_out;

    float *q, *k, *v, *o;
    cudaGetSymbolAddress((void**)&q, g_q);
    cudaGetSymbolAddress((void**)&k, g_k);
    cudaGetSymbolAddress((void**)&v, g_v);
    cudaGetSymbolAddress((void**)&o, g_o);

    cudaFuncSetAttribute((const void*)gemm_bf16x3,
                         cudaFuncAttributeMaxDynamicSharedMemorySize, GEMM_SMEM);
    cudaFuncSetAttribute((const void*)flash_mma_kernel,
                         cudaFuncAttributeMaxDynamicSharedMemorySize, FL_SMEM);

    // QKV projections (tensor-core bf16x3) — R10 launch pattern, DO NOT TOUCH
    gemm_bf16x3<<<dim3(DE / 128, S_LEN / 128), 256, GEMM_SMEM>>>(x, wq, q, S_LEN, DE, DE);
    gemm_bf16x3<<<dim3((HKV * DH) / 128, S_LEN / 128), 256, GEMM_SMEM>>>(x, wk, k, S_LEN, HKV * DH, DE);
    gemm_bf16x3<<<dim3((HKV * DH) / 128, S_LEN / 128), 256, GEMM_SMEM>>>(x, wv, v, S_LEN, HKV * DH, DE);

    // Fused RoPE + plane conversion
    const long rc_total = (long)S_LEN * (HQ + HKV) * 64 + (long)S_LEN * HKV * DH;
    rope_convert_kernel<<<(int)((rc_total + 255) / 256), 256>>>(cs);

    // tensor-core causal flash attention (128-row q tiles, Q frags in regs)
    flash_mma_kernel<<<dim3(S_LEN / 128, HQ), 256, FL_SMEM>>>();

    // output projection
    gemm_bf16x3<<<dim3(DE / 128, S_LEN / 128), 256, GEMM_SMEM>>>(o, wo, out, S_LEN, DE, DE);
}